// round 5
// baseline (speedup 1.0000x reference)
#include <cuda_runtime.h>
#include <math.h>
#include <stdint.h>

#define BSZ   8
#define SEQ   512
#define DIM   768
#define NP    32
#define PE    200
#define EMB   128
#define VOCAB 30522
#define SPAN  20
#define NB    (BSZ*NP)        /* 256 span pairs */
#define NR    (NB*SPAN)       /* 5120 rows */
#define K1    1536            /* 2*DIM */

/* ---------------- scratch (no allocation allowed) ---------------- */
__device__ float g_lr[NB*K1];
__device__ float g_A[NB*DIM];
__device__ float g_P[SPAN*DIM];
__device__ float g_h1[NR*DIM];
__device__ float g_pre2[NR*DIM];
__device__ float g_h2[NR*DIM];
__device__ float g_h3[NR*EMB];
__device__ float g_W1T[DIM*K1];      /* W1[0:1536,:] transposed: [768,1536] */
__device__ float g_W2T[DIM*DIM];     /* W2 transposed: [N,K] */
__device__ float g_WpT[EMB*DIM];     /* Wp transposed: [N,K] */

__device__ __forceinline__ float gelu_exact(float x) {
    return 0.5f * x * (1.0f + erff(x * 0.70710678118654752440f));
}

__device__ __forceinline__ uint32_t f2tf32(float x) {
    uint32_t r;
    asm("cvt.rna.tf32.f32 %0, %1;" : "=r"(r) : "f"(x));
    return r;
}

__device__ __forceinline__ void mma_tf32_16n8k8(float* c, const uint32_t* a, const uint32_t* b) {
    asm volatile(
        "mma.sync.aligned.m16n8k8.row.col.f32.tf32.tf32.f32 "
        "{%0,%1,%2,%3}, {%4,%5,%6,%7}, {%8,%9}, {%0,%1,%2,%3};"
        : "+f"(c[0]), "+f"(c[1]), "+f"(c[2]), "+f"(c[3])
        : "r"(a[0]), "r"(a[1]), "r"(a[2]), "r"(a[3]), "r"(b[0]), "r"(b[1]));
}

/* =================== tf32 mma.sync GEMM ===================
 * C[M, Nvalid] = A[M, K] @ Bt[Nvalid, K]^T (+bias)
 * CTA tile 128 x BN, BK=32, NTHR = BN threads (BN/32 warps, warp tile 64x64,
 * warp grid 2 x BN/64). A row-major (lda), Bt N-major (ldb). K mult of 32.
 * ldc even; stored cols even -> float2 stores 8B aligned.
 */
#define BKP 36   /* BK + 4 pad: fragment loads hit banks 4g+t (all distinct) */

template<int BN>
__global__ void __launch_bounds__(BN, 1)
mgemm(int K, const float* __restrict__ A, int lda,
      const float* __restrict__ Bt, int ldb, int Nvalid,
      float* __restrict__ C, int ldc,
      const float* __restrict__ bias) {
    constexpr int NTHR = BN;
    extern __shared__ __align__(16) float sm[];
    float* As = sm;                 /* [2][128*BKP] */
    float* Bs = sm + 2*128*BKP;     /* [2][BN*BKP]  */

    const int tid  = threadIdx.x;
    const int lane = tid & 31;
    const int wid  = tid >> 5;
    const int wr   = (wid & 1) * 64;   /* warp row offset */
    const int wc   = (wid >> 1) * 64;  /* warp col offset */
    const int g8   = lane >> 2;
    const int t4   = lane & 3;

    const int mBase = blockIdx.y * 128;
    const int nBase = blockIdx.x * BN;
    const int NK = K >> 5;

    float acc[4][8][4];
    #pragma unroll
    for (int i = 0; i < 4; i++)
        #pragma unroll
        for (int j = 0; j < 8; j++)
            #pragma unroll
            for (int q = 0; q < 4; q++) acc[i][j][q] = 0.f;

    const float* Ag = A + (size_t)mBase * lda;

    auto loadA = [&](int s, int kt) {
        float* dst = As + s*128*BKP;
        const float* src = Ag + kt*32;
        #pragma unroll
        for (int i = 0; i < 1024/NTHR; i++) {
            int idx = tid + i*NTHR;
            int r = idx >> 3, c4 = (idx & 7) * 4;
            float4 v = *(const float4*)(src + (size_t)r*lda + c4);
            uint4 u; u.x=f2tf32(v.x); u.y=f2tf32(v.y); u.z=f2tf32(v.z); u.w=f2tf32(v.w);
            *(uint4*)(dst + r*BKP + c4) = u;
        }
    };
    auto loadB = [&](int s, int kt) {
        float* dst = Bs + s*BN*BKP;
        #pragma unroll
        for (int i = 0; i < (BN*8)/NTHR; i++) {
            int idx = tid + i*NTHR;
            int n = idx >> 3, c4 = (idx & 7) * 4;
            int gn = nBase + n;
            float4 v = make_float4(0.f,0.f,0.f,0.f);
            if (gn < Nvalid)
                v = *(const float4*)(Bt + (size_t)gn*ldb + kt*32 + c4);
            uint4 u; u.x=f2tf32(v.x); u.y=f2tf32(v.y); u.z=f2tf32(v.z); u.w=f2tf32(v.w);
            *(uint4*)(dst + n*BKP + c4) = u;
        }
    };

    loadA(0, 0); loadB(0, 0);
    __syncthreads();

    for (int kt = 0; kt < NK; kt++) {
        int s = kt & 1;
        if (kt + 1 < NK) { loadA(s ^ 1, kt + 1); loadB(s ^ 1, kt + 1); }

        const float* as = As + s*128*BKP;
        const float* bs = Bs + s*BN*BKP;
        #pragma unroll
        for (int kk = 0; kk < 32; kk += 8) {
            uint32_t af[4][4], bf[8][2];
            #pragma unroll
            for (int mt = 0; mt < 4; mt++) {
                int r0 = wr + mt*16 + g8;
                const uint32_t* p = (const uint32_t*)(as + r0*BKP + kk + t4);
                af[mt][0] = p[0];
                af[mt][1] = p[8*BKP];
                af[mt][2] = p[4];
                af[mt][3] = p[8*BKP + 4];
            }
            #pragma unroll
            for (int nt = 0; nt < 8; nt++) {
                int n0 = wc + nt*8 + g8;
                const uint32_t* p = (const uint32_t*)(bs + n0*BKP + kk + t4);
                bf[nt][0] = p[0];
                bf[nt][1] = p[4];
            }
            #pragma unroll
            for (int mt = 0; mt < 4; mt++)
                #pragma unroll
                for (int nt = 0; nt < 8; nt++)
                    mma_tf32_16n8k8(acc[mt][nt], af[mt], bf[nt]);
        }
        __syncthreads();
    }

    /* epilogue: fragment -> float2 stores */
    #pragma unroll
    for (int mt = 0; mt < 4; mt++) {
        int r0 = mBase + wr + mt*16 + g8;
        #pragma unroll
        for (int nt = 0; nt < 8; nt++) {
            int cc = nBase + wc + nt*8 + t4*2;
            if (cc < Nvalid) {
                float bx = bias ? bias[cc]   : 0.f;
                float by = bias ? bias[cc+1] : 0.f;
                float2 v0 = make_float2(acc[mt][nt][0] + bx, acc[mt][nt][1] + by);
                float2 v1 = make_float2(acc[mt][nt][2] + bx, acc[mt][nt][3] + by);
                *(float2*)(C + (size_t)r0*ldc + cc)     = v0;
                *(float2*)(C + (size_t)(r0+8)*ldc + cc) = v1;
            }
        }
    }
}

/* =================== misc kernels =================== */
__global__ void k_gather(const float* __restrict__ hs, const int* __restrict__ pairs) {
    int p = blockIdx.x;
    int l0 = pairs[p*2 + 0];
    int r0 = pairs[p*2 + 1];
    int b  = p / NP;
    const float* hl = hs + ((size_t)b*SEQ + l0)*DIM;
    const float* hr = hs + ((size_t)b*SEQ + r0)*DIM;
    float* dst = g_lr + (size_t)p*K1;
    for (int k = threadIdx.x; k < DIM; k += blockDim.x) {
        dst[k]       = hl[k];
        dst[DIM + k] = hr[k];
    }
}

/* P[l] = pos_emb[l] @ W1[1536:1736] + b1 ; grid (SPAN, 6), block 128 */
__global__ void k_posproj(const float* __restrict__ pos, const float* __restrict__ W1,
                          const float* __restrict__ b1) {
    __shared__ float sp[PE];
    int l = blockIdx.x;
    for (int t = threadIdx.x; t < PE; t += blockDim.x) sp[t] = pos[l*PE + t];
    __syncthreads();
    int j = blockIdx.y * 128 + threadIdx.x;
    float acc = b1[j];
    const float* w = W1 + (size_t)K1*DIM + j;
    #pragma unroll 8
    for (int t = 0; t < PE; t++) acc += sp[t] * w[(size_t)t*DIM];
    g_P[l*DIM + j] = acc;
}

/* transpose: out[c*R + r] = in[r*C + c]; R,C multiples of 32 */
__global__ void k_transpose(const float* __restrict__ in, float* __restrict__ out, int R, int C) {
    __shared__ float t[32][33];
    int c0 = blockIdx.x*32, r0 = blockIdx.y*32;
    for (int dy = threadIdx.y; dy < 32; dy += 8)
        t[dy][threadIdx.x] = in[(size_t)(r0+dy)*C + c0 + threadIdx.x];
    __syncthreads();
    for (int dy = threadIdx.y; dy < 32; dy += 8)
        out[(size_t)(c0+dy)*R + r0 + threadIdx.x] = t[threadIdx.x][dy];
}

__device__ __forceinline__ void block_reduce2(float& s, float& sq) {
    __shared__ float ss[8], ssq[8];
    #pragma unroll
    for (int o = 16; o > 0; o >>= 1) {
        s  += __shfl_xor_sync(0xffffffffu, s,  o);
        sq += __shfl_xor_sync(0xffffffffu, sq, o);
    }
    int w = threadIdx.x >> 5;
    if ((threadIdx.x & 31) == 0) { ss[w] = s; ssq[w] = sq; }
    __syncthreads();
    s = 0.f; sq = 0.f;
    #pragma unroll
    for (int i = 0; i < 8; i++) { s += ss[i]; sq += ssq[i]; }
}

__global__ void k_fuse1(const float* __restrict__ g1, const float* __restrict__ be1) {
    int r = blockIdx.x;
    int p = r / SPAN, l = r % SPAN;
    const float* Ap = g_A + (size_t)p*DIM;
    const float* Pl = g_P + (size_t)l*DIM;
    float v[3];
    float s = 0.f, sq = 0.f;
    int j0 = threadIdx.x;
    #pragma unroll
    for (int t = 0; t < 3; t++) {
        int j = j0 + t*256;
        float x = gelu_exact(Ap[j] + Pl[j]);
        v[t] = x; s += x; sq += x*x;
    }
    block_reduce2(s, sq);
    float mean = s * (1.0f/DIM);
    float var  = sq * (1.0f/DIM) - mean*mean;
    float rstd = rsqrtf(var + 1e-12f);
    float* out = g_h1 + (size_t)r*DIM;
    #pragma unroll
    for (int t = 0; t < 3; t++) {
        int j = j0 + t*256;
        out[j] = (v[t] - mean) * rstd * g1[j] + be1[j];
    }
}

__global__ void k_gelu_ln(const float* __restrict__ in, float* __restrict__ out,
                          const float* __restrict__ g, const float* __restrict__ be) {
    int r = blockIdx.x;
    const float* ip = in + (size_t)r*DIM;
    float v[3];
    float s = 0.f, sq = 0.f;
    int j0 = threadIdx.x;
    #pragma unroll
    for (int t = 0; t < 3; t++) {
        int j = j0 + t*256;
        float x = gelu_exact(ip[j]);
        v[t] = x; s += x; sq += x*x;
    }
    block_reduce2(s, sq);
    float mean = s * (1.0f/DIM);
    float var  = sq * (1.0f/DIM) - mean*mean;
    float rstd = rsqrtf(var + 1e-12f);
    float* op = out + (size_t)r*DIM;
    #pragma unroll
    for (int t = 0; t < 3; t++) {
        int j = j0 + t*256;
        op[j] = (v[t] - mean) * rstd * g[j] + be[j];
    }
}

/* ---------------- host launch ---------------- */
extern "C" void kernel_launch(void* const* d_in, const int* in_sizes, int n_in,
                              void* d_out, int out_size) {
    const float* hs    = (const float*)d_in[0];
    const int*   pairs = (const int*)  d_in[1];
    const float* pos   = (const float*)d_in[2];
    const float* W1    = (const float*)d_in[3];
    const float* b1    = (const float*)d_in[4];
    const float* g1    = (const float*)d_in[5];
    const float* be1   = (const float*)d_in[6];
    const float* W2    = (const float*)d_in[7];
    const float* b2    = (const float*)d_in[8];
    const float* g2    = (const float*)d_in[9];
    const float* be2   = (const float*)d_in[10];
    const float* Wp    = (const float*)d_in[11];
    const float* bp    = (const float*)d_in[12];
    const float* Wdec  = (const float*)d_in[13];
    float* out = (float*)d_out;
    (void)in_sizes; (void)n_in; (void)out_size;

    float *p_lr, *p_A, *p_h1, *p_pre2, *p_h2, *p_h3, *p_W1T, *p_W2T, *p_WpT;
    cudaGetSymbolAddress((void**)&p_lr,   g_lr);
    cudaGetSymbolAddress((void**)&p_A,    g_A);
    cudaGetSymbolAddress((void**)&p_h1,   g_h1);
    cudaGetSymbolAddress((void**)&p_pre2, g_pre2);
    cudaGetSymbolAddress((void**)&p_h2,   g_h2);
    cudaGetSymbolAddress((void**)&p_h3,   g_h3);
    cudaGetSymbolAddress((void**)&p_W1T,  g_W1T);
    cudaGetSymbolAddress((void**)&p_W2T,  g_W2T);
    cudaGetSymbolAddress((void**)&p_WpT,  g_WpT);

    const int SM128 = (2*128*BKP + 2*128*BKP) * 4;   /* 73728  */
    const int SM256 = (2*128*BKP + 2*256*BKP) * 4;   /* 110592 */
    cudaFuncSetAttribute(mgemm<128>, cudaFuncAttributeMaxDynamicSharedMemorySize, SM128);
    cudaFuncSetAttribute(mgemm<256>, cudaFuncAttributeMaxDynamicSharedMemorySize, SM256);

    /* 0) transposes so all tensor GEMMs are NT */
    k_transpose<<<dim3(DIM/32, K1/32), dim3(32,8)>>>(W1, p_W1T, K1, DIM);
    k_transpose<<<dim3(DIM/32, DIM/32), dim3(32,8)>>>(W2, p_W2T, DIM, DIM);
    k_transpose<<<dim3(EMB/32, DIM/32), dim3(32,8)>>>(Wp, p_WpT, DIM, EMB);

    /* 1) gather [lh, rh] rows */
    k_gather<<<NB, 256>>>(hs, pairs);

    /* 2) P = pos_emb @ W1c + b1 */
    k_posproj<<<dim3(SPAN, DIM/128), 128>>>(pos, W1, b1);

    /* 3) A = g_lr @ W1[0:1536]  (tf32 mma) */
    mgemm<128><<<dim3(DIM/128, NB/128), 128, SM128>>>(
        K1, p_lr, K1, p_W1T, K1, DIM, p_A, DIM, nullptr);

    /* 4) h1 = LN(gelu(A + P)) */
    k_fuse1<<<NR, 256>>>(g1, be1);

    /* 5) pre2 = h1 @ W2 + b2, h2 = LN(gelu(pre2)) */
    mgemm<256><<<dim3(DIM/256, NR/128), 256, SM256>>>(
        DIM, p_h1, DIM, p_W2T, DIM, DIM, p_pre2, DIM, b2);
    k_gelu_ln<<<NR, 256>>>(p_pre2, p_h2, g2, be2);

    /* 6) h3 = h2 @ Wp + bp */
    mgemm<128><<<dim3(EMB/128, NR/128), 128, SM128>>>(
        DIM, p_h2, DIM, p_WpT, DIM, EMB, p_h3, EMB, bp);

    /* 7) out = h3 @ Wdec^T (M=5120 N=30522 K=128) */
    mgemm<256><<<dim3((VOCAB + 255)/256, NR/128), 256, SM256>>>(
        EMB, p_h3, EMB, Wdec, EMB, VOCAB, out, VOCAB, nullptr);
}

// round 6
// speedup vs baseline: 1.2164x; 1.2164x over previous
#include <cuda_runtime.h>
#include <math.h>
#include <stdint.h>

#define BSZ   8
#define SEQ   512
#define DIM   768
#define NP    32
#define PE    200
#define EMB   128
#define VOCAB 30522
#define SPAN  20
#define NB    (BSZ*NP)        /* 256 span pairs */
#define NR    (NB*SPAN)       /* 5120 rows */
#define K1    1536            /* 2*DIM */

/* ---------------- scratch (no allocation allowed) ---------------- */
__device__ float g_lr[NB*K1];        /* tf32-rounded */
__device__ float g_A[NB*DIM];
__device__ float g_P[SPAN*DIM];
__device__ float g_h1[NR*DIM];       /* tf32-rounded */
__device__ float g_pre2[NR*DIM];
__device__ float g_h2[NR*DIM];       /* tf32-rounded */
__device__ float g_h3[NR*EMB];       /* tf32-rounded */
__device__ float g_W1T[DIM*K1];      /* tf32-rounded, [768,1536] */
__device__ float g_W2T[DIM*DIM];     /* tf32-rounded */
__device__ float g_WpT[EMB*DIM];     /* tf32-rounded */
__device__ float g_Wd[VOCAB*EMB];    /* tf32-rounded Wdec */

__device__ __forceinline__ float gelu_exact(float x) {
    return 0.5f * x * (1.0f + erff(x * 0.70710678118654752440f));
}
__device__ __forceinline__ uint32_t f2tf32(float x) {
    uint32_t r;
    asm("cvt.rna.tf32.f32 %0, %1;" : "=r"(r) : "f"(x));
    return r;
}
__device__ __forceinline__ float rtf(float x) { return __uint_as_float(f2tf32(x)); }

__device__ __forceinline__ void mma_tf32_16n8k8(float* c, const uint32_t* a, const uint32_t* b) {
    asm volatile(
        "mma.sync.aligned.m16n8k8.row.col.f32.tf32.tf32.f32 "
        "{%0,%1,%2,%3}, {%4,%5,%6,%7}, {%8,%9}, {%0,%1,%2,%3};"
        : "+f"(c[0]), "+f"(c[1]), "+f"(c[2]), "+f"(c[3])
        : "r"(a[0]), "r"(a[1]), "r"(a[2]), "r"(a[3]), "r"(b[0]), "r"(b[1]));
}

__device__ __forceinline__ uint32_t smem_u32(const void* p) {
    uint32_t a;
    asm("{ .reg .u64 t; cvta.to.shared.u64 t, %1; cvt.u32.u64 %0, t; }" : "=r"(a) : "l"(p));
    return a;
}

/* =================== tf32 mma.sync GEMM (cp.async pipeline) ===============
 * C[M, Nvalid] = A[M, K] @ Bt[Nvalid, K]^T (+bias)
 * All A/Bt elements must already be tf32-rounded.
 * CTA tile 128x128, BK=32, 128 thr, 4 warps (warp tile 64x64). K mult of 32.
 * ldc even; stored cols even -> float2 stores 8B aligned.
 */
#define BKP 36   /* BK + 4 pad */

__global__ void __launch_bounds__(128, 2)
mgemm(int K, const float* __restrict__ A, int lda,
      const float* __restrict__ Bt, int ldb, int Nvalid,
      float* __restrict__ C, int ldc,
      const float* __restrict__ bias, int round_out) {
    extern __shared__ __align__(16) float sm[];
    float* As = sm;                 /* [2][128*BKP] */
    float* Bs = sm + 2*128*BKP;     /* [2][128*BKP] */
    const uint32_t sbA = smem_u32(As);
    const uint32_t sbB = smem_u32(Bs);

    const int tid  = threadIdx.x;
    const int lane = tid & 31;
    const int wid  = tid >> 5;
    const int wr   = (wid & 1) * 64;
    const int wc   = (wid >> 1) * 64;
    const int g8   = lane >> 2;
    const int t4   = lane & 3;

    const int mBase = blockIdx.y * 128;
    const int nBase = blockIdx.x * 128;
    const int NK = K >> 5;

    float acc[4][8][4];
    #pragma unroll
    for (int i = 0; i < 4; i++)
        #pragma unroll
        for (int j = 0; j < 8; j++)
            #pragma unroll
            for (int q = 0; q < 4; q++) acc[i][j][q] = 0.f;

    const float* Ag = A + (size_t)mBase * lda;

    auto loadA = [&](int s, int kt) {
        uint32_t dst = sbA + (uint32_t)(s*128*BKP)*4u;
        const float* src = Ag + kt*32;
        #pragma unroll
        for (int i = 0; i < 8; i++) {
            int idx = tid + i*128;
            int r = idx >> 3, c4 = (idx & 7) * 4;
            uint32_t d = dst + (uint32_t)(r*BKP + c4)*4u;
            const float* g = src + (size_t)r*lda + c4;
            asm volatile("cp.async.cg.shared.global [%0], [%1], 16;" :: "r"(d), "l"(g));
        }
    };
    auto loadB = [&](int s, int kt) {
        uint32_t dst = sbB + (uint32_t)(s*128*BKP)*4u;
        #pragma unroll
        for (int i = 0; i < 8; i++) {
            int idx = tid + i*128;
            int n = idx >> 3, c4 = (idx & 7) * 4;
            int gn = nBase + n;
            uint32_t d = dst + (uint32_t)(n*BKP + c4)*4u;
            const float* g = Bt + (size_t)gn*ldb + kt*32 + c4;
            int sz = (gn < Nvalid) ? 16 : 0;   /* OOB rows -> zero fill */
            asm volatile("cp.async.cg.shared.global [%0], [%1], 16, %2;" :: "r"(d), "l"(g), "r"(sz));
        }
    };

    loadA(0, 0); loadB(0, 0);
    asm volatile("cp.async.commit_group;");

    for (int kt = 0; kt < NK; kt++) {
        int s = kt & 1;
        asm volatile("cp.async.wait_group 0;");
        __syncthreads();
        if (kt + 1 < NK) {
            loadA(s ^ 1, kt + 1); loadB(s ^ 1, kt + 1);
            asm volatile("cp.async.commit_group;");
        }

        const float* as = As + s*128*BKP;
        const float* bs = Bs + s*128*BKP;
        #pragma unroll
        for (int kk = 0; kk < 32; kk += 8) {
            uint32_t af[4][4], bf[8][2];
            #pragma unroll
            for (int mt = 0; mt < 4; mt++) {
                int r0 = wr + mt*16 + g8;
                const uint32_t* p = (const uint32_t*)(as + r0*BKP + kk + t4);
                af[mt][0] = p[0];
                af[mt][1] = p[8*BKP];
                af[mt][2] = p[4];
                af[mt][3] = p[8*BKP + 4];
            }
            #pragma unroll
            for (int nt = 0; nt < 8; nt++) {
                int n0 = wc + nt*8 + g8;
                const uint32_t* p = (const uint32_t*)(bs + n0*BKP + kk + t4);
                bf[nt][0] = p[0];
                bf[nt][1] = p[4];
            }
            #pragma unroll
            for (int mt = 0; mt < 4; mt++)
                #pragma unroll
                for (int nt = 0; nt < 8; nt++)
                    mma_tf32_16n8k8(acc[mt][nt], af[mt], bf[nt]);
        }
        __syncthreads();
    }

    /* epilogue */
    #pragma unroll
    for (int mt = 0; mt < 4; mt++) {
        int r0 = mBase + wr + mt*16 + g8;
        #pragma unroll
        for (int nt = 0; nt < 8; nt++) {
            int cc = nBase + wc + nt*8 + t4*2;
            if (cc < Nvalid) {
                float bx = bias ? bias[cc]   : 0.f;
                float by = bias ? bias[cc+1] : 0.f;
                float2 v0 = make_float2(acc[mt][nt][0] + bx, acc[mt][nt][1] + by);
                float2 v1 = make_float2(acc[mt][nt][2] + bx, acc[mt][nt][3] + by);
                if (round_out) {
                    v0.x = rtf(v0.x); v0.y = rtf(v0.y);
                    v1.x = rtf(v1.x); v1.y = rtf(v1.y);
                }
                *(float2*)(C + (size_t)r0*ldc + cc)     = v0;
                *(float2*)(C + (size_t)(r0+8)*ldc + cc) = v1;
            }
        }
    }
}

/* =================== misc kernels =================== */
__global__ void k_gather(const float* __restrict__ hs, const int* __restrict__ pairs) {
    int p = blockIdx.x;
    int l0 = pairs[p*2 + 0];
    int r0 = pairs[p*2 + 1];
    int b  = p / NP;
    const float* hl = hs + ((size_t)b*SEQ + l0)*DIM;
    const float* hr = hs + ((size_t)b*SEQ + r0)*DIM;
    float* dst = g_lr + (size_t)p*K1;
    for (int k = threadIdx.x; k < DIM; k += blockDim.x) {
        dst[k]       = rtf(hl[k]);
        dst[DIM + k] = rtf(hr[k]);
    }
}

/* P[l] = pos_emb[l] @ W1[1536:1736] + b1 ; grid (SPAN, 6), block 128 */
__global__ void k_posproj(const float* __restrict__ pos, const float* __restrict__ W1,
                          const float* __restrict__ b1) {
    __shared__ float sp[PE];
    int l = blockIdx.x;
    for (int t = threadIdx.x; t < PE; t += blockDim.x) sp[t] = pos[l*PE + t];
    __syncthreads();
    int j = blockIdx.y * 128 + threadIdx.x;
    float acc = b1[j];
    const float* w = W1 + (size_t)K1*DIM + j;
    #pragma unroll 8
    for (int t = 0; t < PE; t++) acc += sp[t] * w[(size_t)t*DIM];
    g_P[l*DIM + j] = acc;
}

/* transpose + tf32 round: out[c*R + r] = rtf(in[r*C + c]) */
__global__ void k_transpose(const float* __restrict__ in, float* __restrict__ out, int R, int C) {
    __shared__ float t[32][33];
    int c0 = blockIdx.x*32, r0 = blockIdx.y*32;
    for (int dy = threadIdx.y; dy < 32; dy += 8)
        t[dy][threadIdx.x] = in[(size_t)(r0+dy)*C + c0 + threadIdx.x];
    __syncthreads();
    for (int dy = threadIdx.y; dy < 32; dy += 8)
        out[(size_t)(c0+dy)*R + r0 + threadIdx.x] = rtf(t[threadIdx.x][dy]);
}

/* elementwise tf32-rounded copy (vectorized) */
__global__ void k_cvt(const float* __restrict__ in, float* __restrict__ out, int n4) {
    int i = blockIdx.x*blockDim.x + threadIdx.x;
    if (i < n4) {
        float4 v = ((const float4*)in)[i];
        v.x = rtf(v.x); v.y = rtf(v.y); v.z = rtf(v.z); v.w = rtf(v.w);
        ((float4*)out)[i] = v;
    }
}

__device__ __forceinline__ void block_reduce2(float& s, float& sq) {
    __shared__ float ss[8], ssq[8];
    #pragma unroll
    for (int o = 16; o > 0; o >>= 1) {
        s  += __shfl_xor_sync(0xffffffffu, s,  o);
        sq += __shfl_xor_sync(0xffffffffu, sq, o);
    }
    int w = threadIdx.x >> 5;
    if ((threadIdx.x & 31) == 0) { ss[w] = s; ssq[w] = sq; }
    __syncthreads();
    s = 0.f; sq = 0.f;
    #pragma unroll
    for (int i = 0; i < 8; i++) { s += ss[i]; sq += ssq[i]; }
}

__global__ void k_fuse1(const float* __restrict__ g1, const float* __restrict__ be1) {
    int r = blockIdx.x;
    int p = r / SPAN, l = r % SPAN;
    const float* Ap = g_A + (size_t)p*DIM;
    const float* Pl = g_P + (size_t)l*DIM;
    float v[3];
    float s = 0.f, sq = 0.f;
    int j0 = threadIdx.x;
    #pragma unroll
    for (int t = 0; t < 3; t++) {
        int j = j0 + t*256;
        float x = gelu_exact(Ap[j] + Pl[j]);
        v[t] = x; s += x; sq += x*x;
    }
    block_reduce2(s, sq);
    float mean = s * (1.0f/DIM);
    float var  = sq * (1.0f/DIM) - mean*mean;
    float rstd = rsqrtf(var + 1e-12f);
    float* out = g_h1 + (size_t)r*DIM;
    #pragma unroll
    for (int t = 0; t < 3; t++) {
        int j = j0 + t*256;
        out[j] = rtf((v[t] - mean) * rstd * g1[j] + be1[j]);
    }
}

__global__ void k_gelu_ln(const float* __restrict__ in, float* __restrict__ out,
                          const float* __restrict__ g, const float* __restrict__ be) {
    int r = blockIdx.x;
    const float* ip = in + (size_t)r*DIM;
    float v[3];
    float s = 0.f, sq = 0.f;
    int j0 = threadIdx.x;
    #pragma unroll
    for (int t = 0; t < 3; t++) {
        int j = j0 + t*256;
        float x = gelu_exact(ip[j]);
        v[t] = x; s += x; sq += x*x;
    }
    block_reduce2(s, sq);
    float mean = s * (1.0f/DIM);
    float var  = sq * (1.0f/DIM) - mean*mean;
    float rstd = rsqrtf(var + 1e-12f);
    float* op = out + (size_t)r*DIM;
    #pragma unroll
    for (int t = 0; t < 3; t++) {
        int j = j0 + t*256;
        op[j] = rtf((v[t] - mean) * rstd * g[j] + be[j]);
    }
}

/* ---------------- host launch ---------------- */
extern "C" void kernel_launch(void* const* d_in, const int* in_sizes, int n_in,
                              void* d_out, int out_size) {
    const float* hs    = (const float*)d_in[0];
    const int*   pairs = (const int*)  d_in[1];
    const float* pos   = (const float*)d_in[2];
    const float* W1    = (const float*)d_in[3];
    const float* b1    = (const float*)d_in[4];
    const float* g1    = (const float*)d_in[5];
    const float* be1   = (const float*)d_in[6];
    const float* W2    = (const float*)d_in[7];
    const float* b2    = (const float*)d_in[8];
    const float* g2    = (const float*)d_in[9];
    const float* be2   = (const float*)d_in[10];
    const float* Wp    = (const float*)d_in[11];
    const float* bp    = (const float*)d_in[12];
    const float* Wdec  = (const float*)d_in[13];
    float* out = (float*)d_out;
    (void)in_sizes; (void)n_in; (void)out_size;

    float *p_lr, *p_A, *p_h1, *p_pre2, *p_h2, *p_h3, *p_W1T, *p_W2T, *p_WpT, *p_Wd;
    cudaGetSymbolAddress((void**)&p_lr,   g_lr);
    cudaGetSymbolAddress((void**)&p_A,    g_A);
    cudaGetSymbolAddress((void**)&p_h1,   g_h1);
    cudaGetSymbolAddress((void**)&p_pre2, g_pre2);
    cudaGetSymbolAddress((void**)&p_h2,   g_h2);
    cudaGetSymbolAddress((void**)&p_h3,   g_h3);
    cudaGetSymbolAddress((void**)&p_W1T,  g_W1T);
    cudaGetSymbolAddress((void**)&p_W2T,  g_W2T);
    cudaGetSymbolAddress((void**)&p_WpT,  g_WpT);
    cudaGetSymbolAddress((void**)&p_Wd,   g_Wd);

    const int MSMEM = 4 * 128 * BKP * 4;   /* 73728 B */
    cudaFuncSetAttribute(mgemm, cudaFuncAttributeMaxDynamicSharedMemorySize, MSMEM);

    /* 0) producer-side tf32 rounding: transposes + Wdec convert */
    k_transpose<<<dim3(DIM/32, K1/32), dim3(32,8)>>>(W1, p_W1T, K1, DIM);
    k_transpose<<<dim3(DIM/32, DIM/32), dim3(32,8)>>>(W2, p_W2T, DIM, DIM);
    k_transpose<<<dim3(EMB/32, DIM/32), dim3(32,8)>>>(Wp, p_WpT, DIM, EMB);
    k_cvt<<<(VOCAB*EMB/4 + 255)/256, 256>>>(Wdec, p_Wd, VOCAB*EMB/4);

    /* 1) gather [lh, rh] rows (tf32-rounded) */
    k_gather<<<NB, 256>>>(hs, pairs);

    /* 2) P = pos_emb @ W1c + b1 */
    k_posproj<<<dim3(SPAN, DIM/128), 128>>>(pos, W1, b1);

    /* 3) A = g_lr @ W1[0:1536] */
    mgemm<<<dim3(DIM/128, NB/128), 128, MSMEM>>>(
        K1, p_lr, K1, p_W1T, K1, DIM, p_A, DIM, nullptr, 0);

    /* 4) h1 = LN(gelu(A + P)) (tf32-rounded out) */
    k_fuse1<<<NR, 256>>>(g1, be1);

    /* 5) pre2 = h1 @ W2 + b2 ; h2 = LN(gelu(pre2)) (rounded out) */
    mgemm<<<dim3(DIM/128, NR/128), 128, MSMEM>>>(
        DIM, p_h1, DIM, p_W2T, DIM, DIM, p_pre2, DIM, b2, 0);
    k_gelu_ln<<<NR, 256>>>(p_pre2, p_h2, g2, be2);

    /* 6) h3 = h2 @ Wp + bp (rounded out) */
    mgemm<<<dim3(EMB/128, NR/128), 128, MSMEM>>>(
        DIM, p_h2, DIM, p_WpT, DIM, EMB, p_h3, EMB, bp, 1);

    /* 7) out = h3 @ Wd^T (M=5120 N=30522 K=128) */
    mgemm<<<dim3((VOCAB + 127)/128, NR/128), 128, MSMEM>>>(
        EMB, p_h3, EMB, p_Wd, EMB, VOCAB, out, VOCAB, nullptr, 0);
}

// round 7
// speedup vs baseline: 1.3511x; 1.1107x over previous
#include <cuda_runtime.h>
#include <math.h>
#include <stdint.h>

#define BSZ   8
#define SEQ   512
#define DIM   768
#define NP    32
#define PE    200
#define EMB   128
#define VOCAB 30522
#define SPAN  20
#define NB    (BSZ*NP)        /* 256 span pairs */
#define NR    (NB*SPAN)       /* 5120 rows */
#define K1    1536            /* 2*DIM */

/* ---------------- scratch (no allocation allowed) ---------------- */
__device__ float g_lr[NB*K1];        /* tf32-rounded */
__device__ float g_A[NB*DIM];
__device__ float g_P[SPAN*DIM];
__device__ float g_h1[NR*DIM];       /* tf32-rounded */
__device__ float g_pre2[NR*DIM];     /* also reused as split-K partial scratch */
__device__ float g_h2[NR*DIM];       /* tf32-rounded */
__device__ float g_h3[NR*EMB];       /* tf32-rounded */
__device__ float g_W1T[DIM*K1];      /* tf32-rounded, [768,1536] */
__device__ float g_W2T[DIM*DIM];     /* tf32-rounded */
__device__ float g_WpT[EMB*DIM];     /* tf32-rounded */
__device__ float g_Wd[VOCAB*EMB];    /* tf32-rounded Wdec */

__device__ __forceinline__ float gelu_exact(float x) {
    return 0.5f * x * (1.0f + erff(x * 0.70710678118654752440f));
}
__device__ __forceinline__ uint32_t f2tf32(float x) {
    uint32_t r;
    asm("cvt.rna.tf32.f32 %0, %1;" : "=r"(r) : "f"(x));
    return r;
}
__device__ __forceinline__ float rtf(float x) { return __uint_as_float(f2tf32(x)); }

__device__ __forceinline__ void mma_tf32_16n8k8(float* c, const uint32_t* a, const uint32_t* b) {
    asm volatile(
        "mma.sync.aligned.m16n8k8.row.col.f32.tf32.tf32.f32 "
        "{%0,%1,%2,%3}, {%4,%5,%6,%7}, {%8,%9}, {%0,%1,%2,%3};"
        : "+f"(c[0]), "+f"(c[1]), "+f"(c[2]), "+f"(c[3])
        : "r"(a[0]), "r"(a[1]), "r"(a[2]), "r"(a[3]), "r"(b[0]), "r"(b[1]));
}

__device__ __forceinline__ uint32_t smem_u32(const void* p) {
    uint32_t a;
    asm("{ .reg .u64 t; cvta.to.shared.u64 t, %1; cvt.u32.u64 %0, t; }" : "=r"(a) : "l"(p));
    return a;
}

/* =================== tf32 mma.sync GEMM (3-stage cp.async) ===============
 * C[M, Nvalid] = A[M, K] @ Bt[Nvalid, K]^T (+bias), split-K over blockIdx.z:
 * k-offset = z*K, C += z*czstride.  A/Bt must be tf32-rounded already.
 * CTA tile 128x128, BK=32, 128 thr, 4 warps (warp tile 64x64). K mult of 32.
 * ldc even; stored cols even -> float2 stores 8B aligned.
 */
#define BKP 36   /* BK + 4 pad */

__global__ void __launch_bounds__(128, 2)
mgemm(int K, const float* __restrict__ A, int lda,
      const float* __restrict__ Bt, int ldb, int Nvalid,
      float* __restrict__ C, int ldc,
      const float* __restrict__ bias, int round_out, int czstride) {
    extern __shared__ __align__(16) float sm[];
    float* As = sm;                 /* [3][128*BKP] */
    float* Bs = sm + 3*128*BKP;     /* [3][128*BKP] */
    const uint32_t sbA = smem_u32(As);
    const uint32_t sbB = smem_u32(Bs);

    const int tid  = threadIdx.x;
    const int lane = tid & 31;
    const int wid  = tid >> 5;
    const int wr   = (wid & 1) * 64;
    const int wc   = (wid >> 1) * 64;
    const int g8   = lane >> 2;
    const int t4   = lane & 3;

    const int mBase = blockIdx.y * 128;
    const int nBase = blockIdx.x * 128;
    const int k0    = blockIdx.z * K;
    C += (size_t)blockIdx.z * czstride;
    const int NK = K >> 5;

    float acc[4][8][4];
    #pragma unroll
    for (int i = 0; i < 4; i++)
        #pragma unroll
        for (int j = 0; j < 8; j++)
            #pragma unroll
            for (int q = 0; q < 4; q++) acc[i][j][q] = 0.f;

    const float* Ag = A + (size_t)mBase * lda + k0;
    const float* Bg = Bt + k0;

    auto loadA = [&](int s, int kt) {
        uint32_t dst = sbA + (uint32_t)(s*128*BKP)*4u;
        const float* src = Ag + kt*32;
        #pragma unroll
        for (int i = 0; i < 8; i++) {
            int idx = tid + i*128;
            int r = idx >> 3, c4 = (idx & 7) * 4;
            uint32_t d = dst + (uint32_t)(r*BKP + c4)*4u;
            const float* g = src + (size_t)r*lda + c4;
            asm volatile("cp.async.cg.shared.global [%0], [%1], 16;" :: "r"(d), "l"(g));
        }
    };
    auto loadB = [&](int s, int kt) {
        uint32_t dst = sbB + (uint32_t)(s*128*BKP)*4u;
        #pragma unroll
        for (int i = 0; i < 8; i++) {
            int idx = tid + i*128;
            int n = idx >> 3, c4 = (idx & 7) * 4;
            int gn = nBase + n;
            uint32_t d = dst + (uint32_t)(n*BKP + c4)*4u;
            const float* g = Bg + (size_t)gn*ldb + kt*32 + c4;
            int sz = (gn < Nvalid) ? 16 : 0;   /* OOB rows -> zero fill */
            asm volatile("cp.async.cg.shared.global [%0], [%1], 16, %2;" :: "r"(d), "l"(g), "r"(sz));
        }
    };

    /* prologue: stage tiles 0 and 1 */
    loadA(0, 0); loadB(0, 0);
    asm volatile("cp.async.commit_group;");
    if (NK > 1) {
        loadA(1, 1); loadB(1, 1);
        asm volatile("cp.async.commit_group;");
    }

    int sc = 0;               /* stage of current tile */
    for (int kt = 0; kt < NK; kt++) {
        if (kt + 1 < NK)
            asm volatile("cp.async.wait_group 1;");
        else
            asm volatile("cp.async.wait_group 0;");
        __syncthreads();
        if (kt + 2 < NK) {
            int sn = sc + 2; if (sn >= 3) sn -= 3;
            loadA(sn, kt + 2); loadB(sn, kt + 2);
            asm volatile("cp.async.commit_group;");
        }

        const float* as = As + sc*128*BKP;
        const float* bs = Bs + sc*128*BKP;
        #pragma unroll
        for (int kk = 0; kk < 32; kk += 8) {
            uint32_t af[4][4], bf[8][2];
            #pragma unroll
            for (int mt = 0; mt < 4; mt++) {
                int r0 = wr + mt*16 + g8;
                const uint32_t* p = (const uint32_t*)(as + r0*BKP + kk + t4);
                af[mt][0] = p[0];
                af[mt][1] = p[8*BKP];
                af[mt][2] = p[4];
                af[mt][3] = p[8*BKP + 4];
            }
            #pragma unroll
            for (int nt = 0; nt < 8; nt++) {
                int n0 = wc + nt*8 + g8;
                const uint32_t* p = (const uint32_t*)(bs + n0*BKP + kk + t4);
                bf[nt][0] = p[0];
                bf[nt][1] = p[4];
            }
            #pragma unroll
            for (int mt = 0; mt < 4; mt++)
                #pragma unroll
                for (int nt = 0; nt < 8; nt++)
                    mma_tf32_16n8k8(acc[mt][nt], af[mt], bf[nt]);
        }
        __syncthreads();
        if (++sc == 3) sc = 0;
    }

    /* epilogue */
    #pragma unroll
    for (int mt = 0; mt < 4; mt++) {
        int r0 = mBase + wr + mt*16 + g8;
        #pragma unroll
        for (int nt = 0; nt < 8; nt++) {
            int cc = nBase + wc + nt*8 + t4*2;
            if (cc < Nvalid) {
                float bx = bias ? bias[cc]   : 0.f;
                float by = bias ? bias[cc+1] : 0.f;
                float2 v0 = make_float2(acc[mt][nt][0] + bx, acc[mt][nt][1] + by);
                float2 v1 = make_float2(acc[mt][nt][2] + bx, acc[mt][nt][3] + by);
                if (round_out) {
                    v0.x = rtf(v0.x); v0.y = rtf(v0.y);
                    v1.x = rtf(v1.x); v1.y = rtf(v1.y);
                }
                *(float2*)(C + (size_t)r0*ldc + cc)     = v0;
                *(float2*)(C + (size_t)(r0+8)*ldc + cc) = v1;
            }
        }
    }
}

/* =================== misc kernels =================== */
__global__ void k_gather(const float* __restrict__ hs, const int* __restrict__ pairs) {
    int p = blockIdx.x;
    int l0 = pairs[p*2 + 0];
    int r0 = pairs[p*2 + 1];
    int b  = p / NP;
    const float* hl = hs + ((size_t)b*SEQ + l0)*DIM;
    const float* hr = hs + ((size_t)b*SEQ + r0)*DIM;
    float* dst = g_lr + (size_t)p*K1;
    for (int k = threadIdx.x; k < DIM; k += blockDim.x) {
        dst[k]       = rtf(hl[k]);
        dst[DIM + k] = rtf(hr[k]);
    }
}

/* P[l] = pos_emb[l] @ W1[1536:1736] + b1 ; grid (SPAN, 6), block 128 */
__global__ void k_posproj(const float* __restrict__ pos, const float* __restrict__ W1,
                          const float* __restrict__ b1) {
    __shared__ float sp[PE];
    int l = blockIdx.x;
    for (int t = threadIdx.x; t < PE; t += blockDim.x) sp[t] = pos[l*PE + t];
    __syncthreads();
    int j = blockIdx.y * 128 + threadIdx.x;
    float acc = b1[j];
    const float* w = W1 + (size_t)K1*DIM + j;
    #pragma unroll 8
    for (int t = 0; t < PE; t++) acc += sp[t] * w[(size_t)t*DIM];
    g_P[l*DIM + j] = acc;
}

/* transpose + tf32 round */
__global__ void k_transpose(const float* __restrict__ in, float* __restrict__ out, int R, int C) {
    __shared__ float t[32][33];
    int c0 = blockIdx.x*32, r0 = blockIdx.y*32;
    for (int dy = threadIdx.y; dy < 32; dy += 8)
        t[dy][threadIdx.x] = in[(size_t)(r0+dy)*C + c0 + threadIdx.x];
    __syncthreads();
    for (int dy = threadIdx.y; dy < 32; dy += 8)
        out[(size_t)(c0+dy)*R + r0 + threadIdx.x] = rtf(t[threadIdx.x][dy]);
}

/* elementwise tf32-rounded copy (vectorized) */
__global__ void k_cvt(const float* __restrict__ in, float* __restrict__ out, int n4) {
    int i = blockIdx.x*blockDim.x + threadIdx.x;
    if (i < n4) {
        float4 v = ((const float4*)in)[i];
        v.x = rtf(v.x); v.y = rtf(v.y); v.z = rtf(v.z); v.w = rtf(v.w);
        ((float4*)out)[i] = v;
    }
}

/* reduce 8 split-K partials (scratch) -> g_A */
__global__ void k_reduce8(const float* __restrict__ part) {
    int i = blockIdx.x*blockDim.x + threadIdx.x;
    float s = 0.f;
    #pragma unroll
    for (int z = 0; z < 8; z++) s += part[(size_t)z*(NB*DIM) + i];
    g_A[i] = s;
}

/* reduce 4 split-K partials + bias, tf32 round -> g_h3 */
__global__ void k_reduceh3(const float* __restrict__ part, const float* __restrict__ bp) {
    int i = blockIdx.x*blockDim.x + threadIdx.x;
    float s = bp[i & (EMB-1)];
    #pragma unroll
    for (int z = 0; z < 4; z++) s += part[(size_t)z*(NR*EMB) + i];
    g_h3[i] = rtf(s);
}

__device__ __forceinline__ void block_reduce2(float& s, float& sq) {
    __shared__ float ss[8], ssq[8];
    #pragma unroll
    for (int o = 16; o > 0; o >>= 1) {
        s  += __shfl_xor_sync(0xffffffffu, s,  o);
        sq += __shfl_xor_sync(0xffffffffu, sq, o);
    }
    int w = threadIdx.x >> 5;
    if ((threadIdx.x & 31) == 0) { ss[w] = s; ssq[w] = sq; }
    __syncthreads();
    s = 0.f; sq = 0.f;
    #pragma unroll
    for (int i = 0; i < 8; i++) { s += ss[i]; sq += ssq[i]; }
}

__global__ void k_fuse1(const float* __restrict__ g1, const float* __restrict__ be1) {
    int r = blockIdx.x;
    int p = r / SPAN, l = r % SPAN;
    const float* Ap = g_A + (size_t)p*DIM;
    const float* Pl = g_P + (size_t)l*DIM;
    float v[3];
    float s = 0.f, sq = 0.f;
    int j0 = threadIdx.x;
    #pragma unroll
    for (int t = 0; t < 3; t++) {
        int j = j0 + t*256;
        float x = gelu_exact(Ap[j] + Pl[j]);
        v[t] = x; s += x; sq += x*x;
    }
    block_reduce2(s, sq);
    float mean = s * (1.0f/DIM);
    float var  = sq * (1.0f/DIM) - mean*mean;
    float rstd = rsqrtf(var + 1e-12f);
    float* out = g_h1 + (size_t)r*DIM;
    #pragma unroll
    for (int t = 0; t < 3; t++) {
        int j = j0 + t*256;
        out[j] = rtf((v[t] - mean) * rstd * g1[j] + be1[j]);
    }
}

__global__ void k_gelu_ln(const float* __restrict__ in, float* __restrict__ out,
                          const float* __restrict__ g, const float* __restrict__ be) {
    int r = blockIdx.x;
    const float* ip = in + (size_t)r*DIM;
    float v[3];
    float s = 0.f, sq = 0.f;
    int j0 = threadIdx.x;
    #pragma unroll
    for (int t = 0; t < 3; t++) {
        int j = j0 + t*256;
        float x = gelu_exact(ip[j]);
        v[t] = x; s += x; sq += x*x;
    }
    block_reduce2(s, sq);
    float mean = s * (1.0f/DIM);
    float var  = sq * (1.0f/DIM) - mean*mean;
    float rstd = rsqrtf(var + 1e-12f);
    float* op = out + (size_t)r*DIM;
    #pragma unroll
    for (int t = 0; t < 3; t++) {
        int j = j0 + t*256;
        op[j] = rtf((v[t] - mean) * rstd * g[j] + be[j]);
    }
}

/* ---------------- host launch ---------------- */
extern "C" void kernel_launch(void* const* d_in, const int* in_sizes, int n_in,
                              void* d_out, int out_size) {
    const float* hs    = (const float*)d_in[0];
    const int*   pairs = (const int*)  d_in[1];
    const float* pos   = (const float*)d_in[2];
    const float* W1    = (const float*)d_in[3];
    const float* b1    = (const float*)d_in[4];
    const float* g1    = (const float*)d_in[5];
    const float* be1   = (const float*)d_in[6];
    const float* W2    = (const float*)d_in[7];
    const float* b2    = (const float*)d_in[8];
    const float* g2    = (const float*)d_in[9];
    const float* be2   = (const float*)d_in[10];
    const float* Wp    = (const float*)d_in[11];
    const float* bp    = (const float*)d_in[12];
    const float* Wdec  = (const float*)d_in[13];
    float* out = (float*)d_out;
    (void)in_sizes; (void)n_in; (void)out_size;

    float *p_lr, *p_A, *p_h1, *p_pre2, *p_h2, *p_h3, *p_W1T, *p_W2T, *p_WpT, *p_Wd;
    cudaGetSymbolAddress((void**)&p_lr,   g_lr);
    cudaGetSymbolAddress((void**)&p_A,    g_A);
    cudaGetSymbolAddress((void**)&p_h1,   g_h1);
    cudaGetSymbolAddress((void**)&p_pre2, g_pre2);
    cudaGetSymbolAddress((void**)&p_h2,   g_h2);
    cudaGetSymbolAddress((void**)&p_h3,   g_h3);
    cudaGetSymbolAddress((void**)&p_W1T,  g_W1T);
    cudaGetSymbolAddress((void**)&p_W2T,  g_W2T);
    cudaGetSymbolAddress((void**)&p_WpT,  g_WpT);
    cudaGetSymbolAddress((void**)&p_Wd,   g_Wd);

    const int MSMEM = 6 * 128 * BKP * 4;   /* 3 stages x (A+B) = 110592 B */
    cudaFuncSetAttribute(mgemm, cudaFuncAttributeMaxDynamicSharedMemorySize, MSMEM);

    /* 0) producer-side tf32 rounding: transposes + Wdec convert */
    k_transpose<<<dim3(DIM/32, K1/32), dim3(32,8)>>>(W1, p_W1T, K1, DIM);
    k_transpose<<<dim3(DIM/32, DIM/32), dim3(32,8)>>>(W2, p_W2T, DIM, DIM);
    k_transpose<<<dim3(EMB/32, DIM/32), dim3(32,8)>>>(Wp, p_WpT, DIM, EMB);
    k_cvt<<<(VOCAB*EMB/4 + 255)/256, 256>>>(Wdec, p_Wd, VOCAB*EMB/4);

    /* 1) gather [lh, rh] rows (tf32-rounded) */
    k_gather<<<NB, 256>>>(hs, pairs);

    /* 2) P = pos_emb @ W1c + b1 */
    k_posproj<<<dim3(SPAN, DIM/128), 128>>>(pos, W1, b1);

    /* 3) A = g_lr @ W1[0:1536]  split-K x8 (partials in g_pre2 scratch) */
    mgemm<<<dim3(DIM/128, NB/128, 8), 128, MSMEM>>>(
        K1/8, p_lr, K1, p_W1T, K1, DIM, p_pre2, DIM, nullptr, 0, NB*DIM);
    k_reduce8<<<(NB*DIM)/256, 256>>>(p_pre2);

    /* 4) h1 = LN(gelu(A + P)) (tf32-rounded out) */
    k_fuse1<<<NR, 256>>>(g1, be1);

    /* 5) pre2 = h1 @ W2 + b2 ; h2 = LN(gelu(pre2)) (rounded out) */
    mgemm<<<dim3(DIM/128, NR/128, 1), 128, MSMEM>>>(
        DIM, p_h1, DIM, p_W2T, DIM, DIM, p_pre2, DIM, b2, 0, 0);
    k_gelu_ln<<<NR, 256>>>(p_pre2, p_h2, g2, be2);

    /* 6) h3 = h2 @ Wp + bp  split-K x4 (partials in g_pre2 scratch) */
    mgemm<<<dim3(EMB/128, NR/128, 4), 128, MSMEM>>>(
        DIM/4, p_h2, DIM, p_WpT, DIM, EMB, p_pre2, EMB, nullptr, 0, NR*EMB);
    k_reduceh3<<<(NR*EMB)/256, 256>>>(p_pre2, bp);

    /* 7) out = h3 @ Wd^T (M=5120 N=30522 K=128) */
    mgemm<<<dim3((VOCAB + 127)/128, NR/128, 1), 128, MSMEM>>>(
        EMB, p_h3, EMB, p_Wd, EMB, VOCAB, out, VOCAB, nullptr, 0, 0);
}

// round 8
// speedup vs baseline: 1.3830x; 1.0236x over previous
#include <cuda_runtime.h>
#include <math.h>
#include <stdint.h>

#define BSZ   8
#define SEQ   512
#define DIM   768
#define NP    32
#define PE    200
#define EMB   128
#define VOCAB 30522
#define SPAN  20
#define NB    (BSZ*NP)        /* 256 span pairs */
#define NR    (NB*SPAN)       /* 5120 rows */
#define K1    1536            /* 2*DIM */
#define VROWS 30592           /* 239*128, padded vocab rows */

/* ---------------- scratch (no allocation allowed) ---------------- */
/* FRAG layout (mma-fragment tiled) for all mma-consumed buffers */
__device__ __align__(256) float g_lr[NB*K1];
__device__ __align__(256) float g_h1[NR*DIM];
__device__ __align__(256) float g_h2[NR*DIM];
__device__ __align__(256) float g_h3[NR*EMB];
__device__ __align__(256) float g_W1T[DIM*K1];
__device__ __align__(256) float g_W2T[DIM*DIM];
__device__ __align__(256) float g_WpT[EMB*DIM];
__device__ __align__(256) float g_Wd[VROWS*EMB];
/* plain layout */
__device__ float g_A[NB*DIM];
__device__ float g_P[SPAN*DIM];
__device__ float g_pre2[NR*DIM];     /* also split-K partial scratch */

/* FRAG addressing: block = (16 rows x 8 k), 128 floats;
 * within block: srow=r&7, u=(r>>3)&1, t=k&3, h=(k>>2)&1
 * offset = srow*16 + t*4 + (u + 2h); quad {r,k},{r+8,k},{r,k+4},{r+8,k+4} contiguous */
__device__ __forceinline__ size_t frag_addr(int r, int k, int ld) {
    return ((size_t)((r >> 4) * (ld >> 3) + (k >> 3)) << 7)
         + ((r & 7) << 4) + ((k & 3) << 2) + ((r >> 3) & 1) + (((k >> 2) & 1) << 1);
}

__device__ __forceinline__ float gelu_exact(float x) {
    return 0.5f * x * (1.0f + erff(x * 0.70710678118654752440f));
}
__device__ __forceinline__ uint32_t f2tf32(float x) {
    uint32_t r;
    asm("cvt.rna.tf32.f32 %0, %1;" : "=r"(r) : "f"(x));
    return r;
}
__device__ __forceinline__ float rtf(float x) { return __uint_as_float(f2tf32(x)); }

__device__ __forceinline__ void mma_tf32_16n8k8(float* c, const uint32_t* a, const uint32_t* b) {
    asm volatile(
        "mma.sync.aligned.m16n8k8.row.col.f32.tf32.tf32.f32 "
        "{%0,%1,%2,%3}, {%4,%5,%6,%7}, {%8,%9}, {%0,%1,%2,%3};"
        : "+f"(c[0]), "+f"(c[1]), "+f"(c[2]), "+f"(c[3])
        : "r"(a[0]), "r"(a[1]), "r"(a[2]), "r"(a[3]), "r"(b[0]), "r"(b[1]));
}

__device__ __forceinline__ uint32_t smem_u32(const void* p) {
    uint32_t a;
    asm("{ .reg .u64 t; cvta.to.shared.u64 t, %1; cvt.u32.u64 %0, t; }" : "=r"(a) : "l"(p));
    return a;
}

/* =================== tf32 mma.sync GEMM (FRAG operands, 3-stage cp.async) ==
 * C[M, Nvalid] = A[M, K] @ Bt[N, K]^T (+bias); A, Bt in FRAG layout with
 * row counts multiple of 16 (B padded; no load guards). Split-K via blockIdx.z.
 * CTA tile 128x128, BK=32, 128 thr, 4 warps (warp tile 64x64). K mult of 32.
 * C written plain; ldc even, stored cols even -> float2 stores 8B aligned.
 * Stage = A(4096 floats) + B(4096 floats) = 32KB; 3 stages = 96KB.
 */
__global__ void __launch_bounds__(128, 2)
mgemm(int K, const float* __restrict__ A, int lda,
      const float* __restrict__ Bt, int ldb, int Nvalid,
      float* __restrict__ C, int ldc,
      const float* __restrict__ bias, int round_out, int czstride) {
    extern __shared__ __align__(16) float sm[];
    float* As = sm;                 /* [3][4096] */
    float* Bs = sm + 3*4096;        /* [3][4096] */
    const uint32_t sbA = smem_u32(As);
    const uint32_t sbB = smem_u32(Bs);

    const int tid  = threadIdx.x;
    const int lane = tid & 31;
    const int wid  = tid >> 5;
    const int wr   = (wid & 1) * 64;
    const int wc   = (wid >> 1) * 64;
    const int wrS  = (wid & 1) * 4;    /* wr>>4 */
    const int wcS  = (wid >> 1) * 4;   /* wc>>4 */
    const int g8   = lane >> 2;
    const int t4   = lane & 3;

    const int mBase = blockIdx.y * 128;
    const int nBase = blockIdx.x * 128;
    const int mSlab = mBase >> 4;
    const int nSlab = nBase >> 4;
    const int k0    = blockIdx.z * K;
    C += (size_t)blockIdx.z * czstride;
    const int NK   = K >> 5;
    const int ldaB = lda >> 3;
    const int ldbB = ldb >> 3;

    float acc[4][8][4];
    #pragma unroll
    for (int i = 0; i < 4; i++)
        #pragma unroll
        for (int j = 0; j < 8; j++)
            #pragma unroll
            for (int q = 0; q < 4; q++) acc[i][j][q] = 0.f;

    auto loadA = [&](int s, int kt) {
        const int kbase = (k0 >> 3) + kt*4;
        #pragma unroll
        for (int i = 0; i < 8; i++) {
            int idx  = tid + i*128;
            int slab = idx >> 7;
            int kb   = (idx >> 5) & 3;
            int g    = idx & 31;
            const float* src = A + (((size_t)(mSlab + slab)*ldaB + (kbase + kb)) << 7) + g*4;
            uint32_t d = sbA + (uint32_t)(s*4096 + ((slab << 2) + kb)*128 + g*4)*4u;
            asm volatile("cp.async.cg.shared.global [%0], [%1], 16;" :: "r"(d), "l"(src));
        }
    };
    auto loadB = [&](int s, int kt) {
        const int kbase = (k0 >> 3) + kt*4;
        #pragma unroll
        for (int i = 0; i < 8; i++) {
            int idx  = tid + i*128;
            int slab = idx >> 7;
            int kb   = (idx >> 5) & 3;
            int g    = idx & 31;
            const float* src = Bt + (((size_t)(nSlab + slab)*ldbB + (kbase + kb)) << 7) + g*4;
            uint32_t d = sbB + (uint32_t)(s*4096 + ((slab << 2) + kb)*128 + g*4)*4u;
            asm volatile("cp.async.cg.shared.global [%0], [%1], 16;" :: "r"(d), "l"(src));
        }
    };

    loadA(0, 0); loadB(0, 0);
    asm volatile("cp.async.commit_group;");
    if (NK > 1) {
        loadA(1, 1); loadB(1, 1);
        asm volatile("cp.async.commit_group;");
    }

    const int lo = g8*16 + t4*4;
    int sc = 0;
    for (int kt = 0; kt < NK; kt++) {
        if (kt + 1 < NK)
            asm volatile("cp.async.wait_group 1;");
        else
            asm volatile("cp.async.wait_group 0;");
        __syncthreads();
        if (kt + 2 < NK) {
            int sn = sc + 2; if (sn >= 3) sn -= 3;
            loadA(sn, kt + 2); loadB(sn, kt + 2);
            asm volatile("cp.async.commit_group;");
        }

        const float* as = As + sc*4096;
        const float* bs = Bs + sc*4096;
        #pragma unroll
        for (int kb = 0; kb < 4; kb++) {
            uint4 aq[4], bq[4];
            #pragma unroll
            for (int mt = 0; mt < 4; mt++)
                aq[mt] = *(const uint4*)(as + (((wrS + mt) << 2) + kb)*128 + lo);
            #pragma unroll
            for (int p = 0; p < 4; p++)
                bq[p] = *(const uint4*)(bs + (((wcS + p) << 2) + kb)*128 + lo);
            #pragma unroll
            for (int mt = 0; mt < 4; mt++) {
                #pragma unroll
                for (int p = 0; p < 4; p++) {
                    uint32_t b0[2] = { bq[p].x, bq[p].z };
                    uint32_t b1[2] = { bq[p].y, bq[p].w };
                    mma_tf32_16n8k8(acc[mt][2*p],   (const uint32_t*)&aq[mt], b0);
                    mma_tf32_16n8k8(acc[mt][2*p+1], (const uint32_t*)&aq[mt], b1);
                }
            }
        }
        __syncthreads();
        if (++sc == 3) sc = 0;
    }

    /* epilogue: plain C */
    #pragma unroll
    for (int mt = 0; mt < 4; mt++) {
        int r0 = mBase + wr + mt*16 + g8;
        #pragma unroll
        for (int nt = 0; nt < 8; nt++) {
            int cc = nBase + wc + nt*8 + t4*2;
            if (cc < Nvalid) {
                float bx = bias ? bias[cc]   : 0.f;
                float by = bias ? bias[cc+1] : 0.f;
                float2 v0 = make_float2(acc[mt][nt][0] + bx, acc[mt][nt][1] + by);
                float2 v1 = make_float2(acc[mt][nt][2] + bx, acc[mt][nt][3] + by);
                if (round_out) {
                    v0.x = rtf(v0.x); v0.y = rtf(v0.y);
                    v1.x = rtf(v1.x); v1.y = rtf(v1.y);
                }
                *(float2*)(C + (size_t)r0*ldc + cc)     = v0;
                *(float2*)(C + (size_t)(r0+8)*ldc + cc) = v1;
            }
        }
    }
}

/* =================== producers (write FRAG) =================== */
__global__ void k_gather(const float* __restrict__ hs, const int* __restrict__ pairs) {
    int p = blockIdx.x;
    int l0 = pairs[p*2 + 0];
    int r0 = pairs[p*2 + 1];
    int b  = p / NP;
    const float* hl = hs + ((size_t)b*SEQ + l0)*DIM;
    const float* hr = hs + ((size_t)b*SEQ + r0)*DIM;
    for (int k = threadIdx.x; k < DIM; k += blockDim.x) {
        g_lr[frag_addr(p, k,       K1)] = rtf(hl[k]);
        g_lr[frag_addr(p, DIM + k, K1)] = rtf(hr[k]);
    }
}

/* P[l] = pos_emb[l] @ W1[1536:1736] + b1 ; grid (SPAN, 6), block 128; plain out */
__global__ void k_posproj(const float* __restrict__ pos, const float* __restrict__ W1,
                          const float* __restrict__ b1) {
    __shared__ float sp[PE];
    int l = blockIdx.x;
    for (int t = threadIdx.x; t < PE; t += blockDim.x) sp[t] = pos[l*PE + t];
    __syncthreads();
    int j = blockIdx.y * 128 + threadIdx.x;
    float acc = b1[j];
    const float* w = W1 + (size_t)K1*DIM + j;
    #pragma unroll 8
    for (int t = 0; t < PE; t++) acc += sp[t] * w[(size_t)t*DIM];
    g_P[l*DIM + j] = acc;
}

/* transpose + tf32 round -> FRAG: out rows = C-dim of in, cols = R-dim */
__global__ void k_transpose(const float* __restrict__ in, float* __restrict__ out, int R, int C) {
    __shared__ float t[32][33];
    int c0 = blockIdx.x*32, r0 = blockIdx.y*32;
    for (int dy = threadIdx.y; dy < 32; dy += 8)
        t[dy][threadIdx.x] = in[(size_t)(r0+dy)*C + c0 + threadIdx.x];
    __syncthreads();
    for (int dy = threadIdx.y; dy < 32; dy += 8)
        out[frag_addr(c0 + dy, r0 + threadIdx.x, R)] = rtf(t[threadIdx.x][dy]);
}

/* Wdec -> FRAG g_Wd with zero pad rows [VOCAB, VROWS); grid exact */
__global__ void k_cvtWd(const float* __restrict__ in) {
    int i = blockIdx.x*256 + threadIdx.x;     /* 0 .. VROWS*EMB-1 */
    int r = i >> 7, k = i & 127;
    float v = (r < VOCAB) ? rtf(in[i]) : 0.f;
    g_Wd[frag_addr(r, k, EMB)] = v;
}

/* reduce 8 split-K partials (scratch) -> g_A (plain) */
__global__ void k_reduce8(const float* __restrict__ part) {
    int i = blockIdx.x*blockDim.x + threadIdx.x;
    float s = 0.f;
    #pragma unroll
    for (int z = 0; z < 8; z++) s += part[(size_t)z*(NB*DIM) + i];
    g_A[i] = s;
}

/* reduce 4 split-K partials + bias, tf32 round -> g_h3 (FRAG) */
__global__ void k_reduceh3(const float* __restrict__ part, const float* __restrict__ bp) {
    int i = blockIdx.x*blockDim.x + threadIdx.x;
    float s = bp[i & (EMB-1)];
    #pragma unroll
    for (int z = 0; z < 4; z++) s += part[(size_t)z*(NR*EMB) + i];
    g_h3[frag_addr(i >> 7, i & 127, EMB)] = rtf(s);
}

__device__ __forceinline__ void block_reduce2(float& s, float& sq) {
    __shared__ float ss[8], ssq[8];
    #pragma unroll
    for (int o = 16; o > 0; o >>= 1) {
        s  += __shfl_xor_sync(0xffffffffu, s,  o);
        sq += __shfl_xor_sync(0xffffffffu, sq, o);
    }
    int w = threadIdx.x >> 5;
    if ((threadIdx.x & 31) == 0) { ss[w] = s; ssq[w] = sq; }
    __syncthreads();
    s = 0.f; sq = 0.f;
    #pragma unroll
    for (int i = 0; i < 8; i++) { s += ss[i]; sq += ssq[i]; }
}

__global__ void k_fuse1(const float* __restrict__ g1, const float* __restrict__ be1) {
    int r = blockIdx.x;
    int p = r / SPAN, l = r % SPAN;
    const float* Ap = g_A + (size_t)p*DIM;
    const float* Pl = g_P + (size_t)l*DIM;
    float v[3];
    float s = 0.f, sq = 0.f;
    int j0 = threadIdx.x;
    #pragma unroll
    for (int t = 0; t < 3; t++) {
        int j = j0 + t*256;
        float x = gelu_exact(Ap[j] + Pl[j]);
        v[t] = x; s += x; sq += x*x;
    }
    block_reduce2(s, sq);
    float mean = s * (1.0f/DIM);
    float var  = sq * (1.0f/DIM) - mean*mean;
    float rstd = rsqrtf(var + 1e-12f);
    #pragma unroll
    for (int t = 0; t < 3; t++) {
        int j = j0 + t*256;
        g_h1[frag_addr(r, j, DIM)] = rtf((v[t] - mean) * rstd * g1[j] + be1[j]);
    }
}

__global__ void k_gelu_ln(const float* __restrict__ in,
                          const float* __restrict__ g, const float* __restrict__ be) {
    int r = blockIdx.x;
    const float* ip = in + (size_t)r*DIM;
    float v[3];
    float s = 0.f, sq = 0.f;
    int j0 = threadIdx.x;
    #pragma unroll
    for (int t = 0; t < 3; t++) {
        int j = j0 + t*256;
        float x = gelu_exact(ip[j]);
        v[t] = x; s += x; sq += x*x;
    }
    block_reduce2(s, sq);
    float mean = s * (1.0f/DIM);
    float var  = sq * (1.0f/DIM) - mean*mean;
    float rstd = rsqrtf(var + 1e-12f);
    #pragma unroll
    for (int t = 0; t < 3; t++) {
        int j = j0 + t*256;
        g_h2[frag_addr(r, j, DIM)] = rtf((v[t] - mean) * rstd * g[j] + be[j]);
    }
}

/* ---------------- host launch ---------------- */
extern "C" void kernel_launch(void* const* d_in, const int* in_sizes, int n_in,
                              void* d_out, int out_size) {
    const float* hs    = (const float*)d_in[0];
    const int*   pairs = (const int*)  d_in[1];
    const float* pos   = (const float*)d_in[2];
    const float* W1    = (const float*)d_in[3];
    const float* b1    = (const float*)d_in[4];
    const float* g1    = (const float*)d_in[5];
    const float* be1   = (const float*)d_in[6];
    const float* W2    = (const float*)d_in[7];
    const float* b2    = (const float*)d_in[8];
    const float* g2    = (const float*)d_in[9];
    const float* be2   = (const float*)d_in[10];
    const float* Wp    = (const float*)d_in[11];
    const float* bp    = (const float*)d_in[12];
    const float* Wdec  = (const float*)d_in[13];
    float* out = (float*)d_out;
    (void)in_sizes; (void)n_in; (void)out_size;

    float *p_lr, *p_h1, *p_pre2, *p_h2, *p_h3, *p_W1T, *p_W2T, *p_WpT, *p_Wd;
    cudaGetSymbolAddress((void**)&p_lr,   g_lr);
    cudaGetSymbolAddress((void**)&p_h1,   g_h1);
    cudaGetSymbolAddress((void**)&p_pre2, g_pre2);
    cudaGetSymbolAddress((void**)&p_h2,   g_h2);
    cudaGetSymbolAddress((void**)&p_h3,   g_h3);
    cudaGetSymbolAddress((void**)&p_W1T,  g_W1T);
    cudaGetSymbolAddress((void**)&p_W2T,  g_W2T);
    cudaGetSymbolAddress((void**)&p_WpT,  g_WpT);
    cudaGetSymbolAddress((void**)&p_Wd,   g_Wd);

    const int MSMEM = 6 * 4096 * 4;   /* 3 stages x (A+B) = 98304 B */
    cudaFuncSetAttribute(mgemm, cudaFuncAttributeMaxDynamicSharedMemorySize, MSMEM);

    /* 0) producer-side tf32 rounding into FRAG layout */
    k_transpose<<<dim3(DIM/32, K1/32), dim3(32,8)>>>(W1, p_W1T, K1, DIM);
    k_transpose<<<dim3(DIM/32, DIM/32), dim3(32,8)>>>(W2, p_W2T, DIM, DIM);
    k_transpose<<<dim3(EMB/32, DIM/32), dim3(32,8)>>>(Wp, p_WpT, DIM, EMB);
    k_cvtWd<<<(VROWS*EMB)/256, 256>>>(Wdec);

    /* 1) gather [lh, rh] rows (FRAG) */
    k_gather<<<NB, 256>>>(hs, pairs);

    /* 2) P = pos_emb @ W1c + b1 */
    k_posproj<<<dim3(SPAN, DIM/128), 128>>>(pos, W1, b1);

    /* 3) A = g_lr @ W1[0:1536]  split-K x8 (partials in g_pre2 scratch) */
    mgemm<<<dim3(DIM/128, NB/128, 8), 128, MSMEM>>>(
        K1/8, p_lr, K1, p_W1T, K1, DIM, p_pre2, DIM, nullptr, 0, NB*DIM);
    k_reduce8<<<(NB*DIM)/256, 256>>>(p_pre2);

    /* 4) h1 = LN(gelu(A + P)) -> FRAG */
    k_fuse1<<<NR, 256>>>(g1, be1);

    /* 5) pre2 = h1 @ W2 + b2 ; h2 = LN(gelu(pre2)) -> FRAG */
    mgemm<<<dim3(DIM/128, NR/128, 1), 128, MSMEM>>>(
        DIM, p_h1, DIM, p_W2T, DIM, DIM, p_pre2, DIM, b2, 0, 0);
    k_gelu_ln<<<NR, 256>>>(p_pre2, g2, be2);

    /* 6) h3 = h2 @ Wp + bp  split-K x4 -> FRAG via reduce */
    mgemm<<<dim3(EMB/128, NR/128, 4), 128, MSMEM>>>(
        DIM/4, p_h2, DIM, p_WpT, DIM, EMB, p_pre2, EMB, nullptr, 0, NR*EMB);
    k_reduceh3<<<(NR*EMB)/256, 256>>>(p_pre2, bp);

    /* 7) out = h3 @ Wd^T (M=5120 N=30522(+pad) K=128) */
    mgemm<<<dim3(VROWS/128, NR/128, 1), 128, MSMEM>>>(
        EMB, p_h3, EMB, p_Wd, EMB, VOCAB, out, VOCAB, nullptr, 0, 0);
}

// round 9
// speedup vs baseline: 1.8709x; 1.3528x over previous
#include <cuda_runtime.h>
#include <cuda_fp16.h>
#include <math.h>
#include <stdint.h>

#define BSZ   8
#define SEQ   512
#define DIM   768
#define NP    32
#define PE    200
#define EMB   128
#define VOCAB 30522
#define SPAN  20
#define NB    (BSZ*NP)        /* 256 span pairs */
#define NR    (NB*SPAN)       /* 5120 rows */
#define K1    1536            /* 2*DIM */
#define VROWS 30592           /* 239*128, padded vocab rows */

/* ---------------- scratch (no allocation allowed) ---------------- */
/* FRAG16 layout (fp16 mma-fragment tiled) for all mma operands */
__device__ __align__(256) __half g_lr[NB*K1];
__device__ __align__(256) __half g_h1[NR*DIM];
__device__ __align__(256) __half g_h2[NR*DIM];
__device__ __align__(256) __half g_h3[NR*EMB];
__device__ __align__(256) __half g_W1T[DIM*K1];
__device__ __align__(256) __half g_W2T[DIM*DIM];
__device__ __align__(256) __half g_WpT[EMB*DIM];
__device__ __align__(256) __half g_Wd[VROWS*EMB];
/* plain fp32 */
__device__ float g_A[NB*DIM];
__device__ float g_P[SPAN*DIM];
__device__ float g_pre2[NR*DIM];     /* also split-K partial scratch */

/* FRAG16 addressing: block = 16 rows x 16 k = 256 halves (512B).
 * Thread granule (16B, 8 halves) at (srow, t4) holds the m16n8k16 A-quad:
 *   b32[0]={(r,kl),(r,kl+1)} b32[1]={(r+8,kl),..} b32[2]={(r,kl+8),..} b32[3]={(r+8,kl+8),..}
 * element offset: srow=r&7, u=(r>>3)&1, t4=(k>>1)&3, h=(k>>3)&1, klo=k&1  */
__device__ __forceinline__ size_t frag16_addr(int r, int k, int ld) {
    size_t blk = (size_t)((r >> 4) * (ld >> 4) + (k >> 4));
    int kk = k & 15;
    return (blk << 8) + (((r & 7) << 2) + ((kk >> 1) & 3)) * 8
         + ((((r >> 3) & 1) + ((kk >> 3) << 1)) << 1) + (kk & 1);
}

__device__ __forceinline__ float gelu_exact(float x) {
    return 0.5f * x * (1.0f + erff(x * 0.70710678118654752440f));
}
__device__ __forceinline__ __half h16(float x) { return __float2half_rn(x); }

__device__ __forceinline__ void mma_f16_16n8k16(float* c, const uint32_t* a,
                                                uint32_t b0, uint32_t b1) {
    asm volatile(
        "mma.sync.aligned.m16n8k16.row.col.f32.f16.f16.f32 "
        "{%0,%1,%2,%3}, {%4,%5,%6,%7}, {%8,%9}, {%0,%1,%2,%3};"
        : "+f"(c[0]), "+f"(c[1]), "+f"(c[2]), "+f"(c[3])
        : "r"(a[0]), "r"(a[1]), "r"(a[2]), "r"(a[3]), "r"(b0), "r"(b1));
}

__device__ __forceinline__ uint32_t smem_u32(const void* p) {
    uint32_t a;
    asm("{ .reg .u64 t; cvta.to.shared.u64 t, %1; cvt.u32.u64 %0, t; }" : "=r"(a) : "l"(p));
    return a;
}

/* =================== fp16 mma.sync GEMM (FRAG16, 3-stage cp.async) =========
 * C[M, Nvalid] = A[M, K] @ Bt[N, K]^T (+bias); A/Bt fp16 FRAG16, row counts
 * multiple of 16 (B padded -> no guards). Split-K via blockIdx.z.
 * CTA 128x128, BK=32, 128 thr, 4 warps (warp tile 64x64). K mult of 32.
 * Stage = (A 4096 + B 4096) halves = 16KB; 3 stages = 48KB; 2 CTAs/SM.
 */
__global__ void __launch_bounds__(128, 2)
mgemm16(int K, const __half* __restrict__ A, int lda,
        const __half* __restrict__ Bt, int ldb, int Nvalid,
        float* __restrict__ C, int ldc,
        const float* __restrict__ bias, int czstride) {
    extern __shared__ __align__(16) __half sm16[];
    __half* As = sm16;              /* [3][4096] */
    __half* Bs = sm16 + 3*4096;     /* [3][4096] */
    const uint32_t sbA = smem_u32(As);
    const uint32_t sbB = smem_u32(Bs);

    const int tid  = threadIdx.x;
    const int lane = tid & 31;
    const int wid  = tid >> 5;
    const int wr   = (wid & 1) * 64;
    const int wc   = (wid >> 1) * 64;
    const int wrS  = (wid & 1) * 4;    /* slab units */
    const int wcS  = (wid >> 1) * 4;
    const int g8   = lane >> 2;
    const int t4   = lane & 3;

    const int mBase = blockIdx.y * 128;
    const int nBase = blockIdx.x * 128;
    const int mSlab = mBase >> 4;
    const int nSlab = nBase >> 4;
    const int k0    = blockIdx.z * K;
    C += (size_t)blockIdx.z * czstride;
    const int NK   = K >> 5;
    const int ldaB = lda >> 4;
    const int ldbB = ldb >> 4;

    float acc[4][8][4];
    #pragma unroll
    for (int i = 0; i < 4; i++)
        #pragma unroll
        for (int j = 0; j < 8; j++)
            #pragma unroll
            for (int q = 0; q < 4; q++) acc[i][j][q] = 0.f;

    /* stage = 512 granules (16B); 128 thr x 4 */
    auto loadA = [&](int s, int kt) {
        const int kbase = (k0 >> 4) + kt*2;
        #pragma unroll
        for (int i = 0; i < 4; i++) {
            int idx  = tid + i*128;          /* 0..511 */
            int slab = idx >> 6;
            int kb   = (idx >> 5) & 1;
            int g    = idx & 31;
            const __half* src = A + (((size_t)(mSlab + slab)*ldaB + (kbase + kb)) << 8) + g*8;
            uint32_t d = sbA + (uint32_t)(s*4096 + ((slab << 1) + kb)*256 + g*8)*2u;
            asm volatile("cp.async.cg.shared.global [%0], [%1], 16;" :: "r"(d), "l"(src));
        }
    };
    auto loadB = [&](int s, int kt) {
        const int kbase = (k0 >> 4) + kt*2;
        #pragma unroll
        for (int i = 0; i < 4; i++) {
            int idx  = tid + i*128;
            int slab = idx >> 6;
            int kb   = (idx >> 5) & 1;
            int g    = idx & 31;
            const __half* src = Bt + (((size_t)(nSlab + slab)*ldbB + (kbase + kb)) << 8) + g*8;
            uint32_t d = sbB + (uint32_t)(s*4096 + ((slab << 1) + kb)*256 + g*8)*2u;
            asm volatile("cp.async.cg.shared.global [%0], [%1], 16;" :: "r"(d), "l"(src));
        }
    };

    loadA(0, 0); loadB(0, 0);
    asm volatile("cp.async.commit_group;");
    if (NK > 1) {
        loadA(1, 1); loadB(1, 1);
        asm volatile("cp.async.commit_group;");
    }

    const int lo = ((g8 << 2) + t4) * 8;
    int sc = 0;
    for (int kt = 0; kt < NK; kt++) {
        if (kt + 1 < NK)
            asm volatile("cp.async.wait_group 1;");
        else
            asm volatile("cp.async.wait_group 0;");
        __syncthreads();
        if (kt + 2 < NK) {
            int sn = sc + 2; if (sn >= 3) sn -= 3;
            loadA(sn, kt + 2); loadB(sn, kt + 2);
            asm volatile("cp.async.commit_group;");
        }

        const __half* as = As + sc*4096;
        const __half* bs = Bs + sc*4096;
        #pragma unroll
        for (int kb = 0; kb < 2; kb++) {
            uint4 aq[4], bq[4];
            #pragma unroll
            for (int mt = 0; mt < 4; mt++)
                aq[mt] = *(const uint4*)(as + (((wrS + mt) << 1) + kb)*256 + lo);
            #pragma unroll
            for (int p = 0; p < 4; p++)
                bq[p] = *(const uint4*)(bs + (((wcS + p) << 1) + kb)*256 + lo);
            #pragma unroll
            for (int mt = 0; mt < 4; mt++) {
                #pragma unroll
                for (int p = 0; p < 4; p++) {
                    mma_f16_16n8k16(acc[mt][2*p],   (const uint32_t*)&aq[mt], bq[p].x, bq[p].z);
                    mma_f16_16n8k16(acc[mt][2*p+1], (const uint32_t*)&aq[mt], bq[p].y, bq[p].w);
                }
            }
        }
        __syncthreads();
        if (++sc == 3) sc = 0;
    }

    /* epilogue: plain fp32 C */
    #pragma unroll
    for (int mt = 0; mt < 4; mt++) {
        int r0 = mBase + wr + mt*16 + g8;
        #pragma unroll
        for (int nt = 0; nt < 8; nt++) {
            int cc = nBase + wc + nt*8 + t4*2;
            if (cc < Nvalid) {
                float bx = bias ? bias[cc]   : 0.f;
                float by = bias ? bias[cc+1] : 0.f;
                float2 v0 = make_float2(acc[mt][nt][0] + bx, acc[mt][nt][1] + by);
                float2 v1 = make_float2(acc[mt][nt][2] + bx, acc[mt][nt][3] + by);
                *(float2*)(C + (size_t)r0*ldc + cc)     = v0;
                *(float2*)(C + (size_t)(r0+8)*ldc + cc) = v1;
            }
        }
    }
}

/* =================== producers (write FRAG16 fp16) =================== */
__global__ void k_gather(const float* __restrict__ hs, const int* __restrict__ pairs) {
    int p = blockIdx.x;
    int l0 = pairs[p*2 + 0];
    int r0 = pairs[p*2 + 1];
    int b  = p / NP;
    const float* hl = hs + ((size_t)b*SEQ + l0)*DIM;
    const float* hr = hs + ((size_t)b*SEQ + r0)*DIM;
    for (int k = threadIdx.x; k < DIM; k += blockDim.x) {
        g_lr[frag16_addr(p, k,       K1)] = h16(hl[k]);
        g_lr[frag16_addr(p, DIM + k, K1)] = h16(hr[k]);
    }
}

/* P[l] = pos_emb[l] @ W1[1536:1736] + b1 ; grid (SPAN, 6), block 128 */
__global__ void k_posproj(const float* __restrict__ pos, const float* __restrict__ W1,
                          const float* __restrict__ b1) {
    __shared__ float sp[PE];
    int l = blockIdx.x;
    for (int t = threadIdx.x; t < PE; t += blockDim.x) sp[t] = pos[l*PE + t];
    __syncthreads();
    int j = blockIdx.y * 128 + threadIdx.x;
    float acc = b1[j];
    const float* w = W1 + (size_t)K1*DIM + j;
    #pragma unroll 8
    for (int t = 0; t < PE; t++) acc += sp[t] * w[(size_t)t*DIM];
    g_P[l*DIM + j] = acc;
}

/* transpose + fp16 round -> FRAG16 */
__global__ void k_transpose(const float* __restrict__ in, __half* __restrict__ out, int R, int C) {
    __shared__ float t[32][33];
    int c0 = blockIdx.x*32, r0 = blockIdx.y*32;
    for (int dy = threadIdx.y; dy < 32; dy += 8)
        t[dy][threadIdx.x] = in[(size_t)(r0+dy)*C + c0 + threadIdx.x];
    __syncthreads();
    for (int dy = threadIdx.y; dy < 32; dy += 8)
        out[frag16_addr(c0 + dy, r0 + threadIdx.x, R)] = h16(t[threadIdx.x][dy]);
}

/* Wdec -> FRAG16 g_Wd, granule-wise (one 16B store per thread), zero pad rows */
__global__ void k_cvtWd(const float* __restrict__ in) {
    int gid = blockIdx.x*256 + threadIdx.x;    /* granule id, 0..VROWS*EMB/8-1 */
    int blk = gid >> 5;
    int g   = gid & 31;
    int srow = g >> 2, t4 = g & 3;
    int R0 = (blk >> 3) << 4;                  /* EMB/16 = 8 k-blocks per row-slab */
    int K0 = (blk & 7) << 4;
    int r0 = R0 + srow, r1 = r0 + 8;
    int kl = K0 + 2*t4, kh = kl + 8;
    float2 a0 = make_float2(0.f,0.f), a1 = a0, a2 = a0, a3 = a0;
    if (r0 < VOCAB) { a0 = *(const float2*)(in + (size_t)r0*EMB + kl);
                      a2 = *(const float2*)(in + (size_t)r0*EMB + kh); }
    if (r1 < VOCAB) { a1 = *(const float2*)(in + (size_t)r1*EMB + kl);
                      a3 = *(const float2*)(in + (size_t)r1*EMB + kh); }
    __half2 h0 = __floats2half2_rn(a0.x, a0.y);
    __half2 h1 = __floats2half2_rn(a1.x, a1.y);
    __half2 h2 = __floats2half2_rn(a2.x, a2.y);
    __half2 h3 = __floats2half2_rn(a3.x, a3.y);
    uint4 u = make_uint4(*(uint32_t*)&h0, *(uint32_t*)&h1, *(uint32_t*)&h2, *(uint32_t*)&h3);
    *(uint4*)(g_Wd + ((size_t)blk << 8) + (size_t)g*8) = u;
}

/* reduce 8 split-K partials (scratch) -> g_A (fp32 plain) */
__global__ void k_reduce8(const float* __restrict__ part) {
    int i = blockIdx.x*blockDim.x + threadIdx.x;
    float s = 0.f;
    #pragma unroll
    for (int z = 0; z < 8; z++) s += part[(size_t)z*(NB*DIM) + i];
    g_A[i] = s;
}

/* reduce 4 split-K partials + bias -> g_h3 (FRAG16) */
__global__ void k_reduceh3(const float* __restrict__ part, const float* __restrict__ bp) {
    int i = blockIdx.x*blockDim.x + threadIdx.x;
    float s = bp[i & (EMB-1)];
    #pragma unroll
    for (int z = 0; z < 4; z++) s += part[(size_t)z*(NR*EMB) + i];
    g_h3[frag16_addr(i >> 7, i & 127, EMB)] = h16(s);
}

__device__ __forceinline__ void block_reduce2(float& s, float& sq) {
    __shared__ float ss[8], ssq[8];
    #pragma unroll
    for (int o = 16; o > 0; o >>= 1) {
        s  += __shfl_xor_sync(0xffffffffu, s,  o);
        sq += __shfl_xor_sync(0xffffffffu, sq, o);
    }
    int w = threadIdx.x >> 5;
    if ((threadIdx.x & 31) == 0) { ss[w] = s; ssq[w] = sq; }
    __syncthreads();
    s = 0.f; sq = 0.f;
    #pragma unroll
    for (int i = 0; i < 8; i++) { s += ss[i]; sq += ssq[i]; }
}

__global__ void k_fuse1(const float* __restrict__ g1, const float* __restrict__ be1) {
    int r = blockIdx.x;
    int p = r / SPAN, l = r % SPAN;
    const float* Ap = g_A + (size_t)p*DIM;
    const float* Pl = g_P + (size_t)l*DIM;
    float v[3];
    float s = 0.f, sq = 0.f;
    int j0 = threadIdx.x;
    #pragma unroll
    for (int t = 0; t < 3; t++) {
        int j = j0 + t*256;
        float x = gelu_exact(Ap[j] + Pl[j]);
        v[t] = x; s += x; sq += x*x;
    }
    block_reduce2(s, sq);
    float mean = s * (1.0f/DIM);
    float var  = sq * (1.0f/DIM) - mean*mean;
    float rstd = rsqrtf(var + 1e-12f);
    #pragma unroll
    for (int t = 0; t < 3; t++) {
        int j = j0 + t*256;
        g_h1[frag16_addr(r, j, DIM)] = h16((v[t] - mean) * rstd * g1[j] + be1[j]);
    }
}

__global__ void k_gelu_ln(const float* __restrict__ in,
                          const float* __restrict__ g, const float* __restrict__ be) {
    int r = blockIdx.x;
    const float* ip = in + (size_t)r*DIM;
    float v[3];
    float s = 0.f, sq = 0.f;
    int j0 = threadIdx.x;
    #pragma unroll
    for (int t = 0; t < 3; t++) {
        int j = j0 + t*256;
        float x = gelu_exact(ip[j]);
        v[t] = x; s += x; sq += x*x;
    }
    block_reduce2(s, sq);
    float mean = s * (1.0f/DIM);
    float var  = sq * (1.0f/DIM) - mean*mean;
    float rstd = rsqrtf(var + 1e-12f);
    #pragma unroll
    for (int t = 0; t < 3; t++) {
        int j = j0 + t*256;
        g_h2[frag16_addr(r, j, DIM)] = h16((v[t] - mean) * rstd * g[j] + be[j]);
    }
}

/* ---------------- host launch ---------------- */
extern "C" void kernel_launch(void* const* d_in, const int* in_sizes, int n_in,
                              void* d_out, int out_size) {
    const float* hs    = (const float*)d_in[0];
    const int*   pairs = (const int*)  d_in[1];
    const float* pos   = (const float*)d_in[2];
    const float* W1    = (const float*)d_in[3];
    const float* b1    = (const float*)d_in[4];
    const float* g1    = (const float*)d_in[5];
    const float* be1   = (const float*)d_in[6];
    const float* W2    = (const float*)d_in[7];
    const float* b2    = (const float*)d_in[8];
    const float* g2    = (const float*)d_in[9];
    const float* be2   = (const float*)d_in[10];
    const float* Wp    = (const float*)d_in[11];
    const float* bp    = (const float*)d_in[12];
    const float* Wdec  = (const float*)d_in[13];
    float* out = (float*)d_out;
    (void)in_sizes; (void)n_in; (void)out_size;

    __half *p_lr, *p_h1, *p_h2, *p_h3, *p_W1T, *p_W2T, *p_WpT, *p_Wd;
    float *p_pre2;
    cudaGetSymbolAddress((void**)&p_lr,   g_lr);
    cudaGetSymbolAddress((void**)&p_h1,   g_h1);
    cudaGetSymbolAddress((void**)&p_h2,   g_h2);
    cudaGetSymbolAddress((void**)&p_h3,   g_h3);
    cudaGetSymbolAddress((void**)&p_W1T,  g_W1T);
    cudaGetSymbolAddress((void**)&p_W2T,  g_W2T);
    cudaGetSymbolAddress((void**)&p_WpT,  g_WpT);
    cudaGetSymbolAddress((void**)&p_Wd,   g_Wd);
    cudaGetSymbolAddress((void**)&p_pre2, g_pre2);

    const int MSMEM = 6 * 4096 * 2;   /* 3 stages x (A+B) = 49152 B */
    cudaFuncSetAttribute(mgemm16, cudaFuncAttributeMaxDynamicSharedMemorySize, MSMEM);

    /* 0) fp16 rounding into FRAG16 */
    k_transpose<<<dim3(DIM/32, K1/32), dim3(32,8)>>>(W1, p_W1T, K1, DIM);
    k_transpose<<<dim3(DIM/32, DIM/32), dim3(32,8)>>>(W2, p_W2T, DIM, DIM);
    k_transpose<<<dim3(EMB/32, DIM/32), dim3(32,8)>>>(Wp, p_WpT, DIM, EMB);
    k_cvtWd<<<(VROWS*EMB/8)/256, 256>>>(Wdec);

    /* 1) gather [lh, rh] rows */
    k_gather<<<NB, 256>>>(hs, pairs);

    /* 2) P = pos_emb @ W1c + b1 */
    k_posproj<<<dim3(SPAN, DIM/128), 128>>>(pos, W1, b1);

    /* 3) A = g_lr @ W1[0:1536]  split-K x8 (partials in g_pre2) */
    mgemm16<<<dim3(DIM/128, NB/128, 8), 128, MSMEM>>>(
        K1/8, p_lr, K1, p_W1T, K1, DIM, p_pre2, DIM, nullptr, NB*DIM);
    k_reduce8<<<(NB*DIM)/256, 256>>>(p_pre2);

    /* 4) h1 = LN(gelu(A + P)) -> FRAG16 */
    k_fuse1<<<NR, 256>>>(g1, be1);

    /* 5) pre2 = h1 @ W2 + b2 ; h2 = LN(gelu(pre2)) -> FRAG16 */
    mgemm16<<<dim3(DIM/128, NR/128, 1), 128, MSMEM>>>(
        DIM, p_h1, DIM, p_W2T, DIM, DIM, p_pre2, DIM, b2, 0);
    k_gelu_ln<<<NR, 256>>>(p_pre2, g2, be2);

    /* 6) h3 = h2 @ Wp + bp  split-K x4 -> FRAG16 via reduce */
    mgemm16<<<dim3(EMB/128, NR/128, 4), 128, MSMEM>>>(
        DIM/4, p_h2, DIM, p_WpT, DIM, EMB, p_pre2, EMB, nullptr, NR*EMB);
    k_reduceh3<<<(NR*EMB)/256, 256>>>(p_pre2, bp);

    /* 7) out = h3 @ Wd^T (M=5120 N=30522(+pad) K=128) */
    mgemm16<<<dim3(VROWS/128, NR/128, 1), 128, MSMEM>>>(
        EMB, p_h3, EMB, p_Wd, EMB, VOCAB, out, VOCAB, nullptr, 0);
}

// round 10
// speedup vs baseline: 1.8711x; 1.0001x over previous
#include <cuda_runtime.h>
#include <cuda_fp16.h>
#include <math.h>
#include <stdint.h>

#define BSZ   8
#define SEQ   512
#define DIM   768
#define NP    32
#define PE    200
#define EMB   128
#define VOCAB 30522
#define SPAN  20
#define NB    (BSZ*NP)        /* 256 span pairs */
#define NR    (NB*SPAN)       /* 5120 rows */
#define K1    1536            /* 2*DIM */
#define VROWS 30592           /* 239*128, padded vocab rows */

/* ---------------- scratch (no allocation allowed) ---------------- */
__device__ __align__(256) __half g_lr[NB*K1];
__device__ __align__(256) __half g_h1[NR*DIM];
__device__ __align__(256) __half g_h2[NR*DIM];
__device__ __align__(256) __half g_h3[NR*EMB];
__device__ __align__(256) __half g_W1T[DIM*K1];
__device__ __align__(256) __half g_W2T[DIM*DIM];
__device__ __align__(256) __half g_WpT[EMB*DIM];
__device__ __align__(256) __half g_Wd[VROWS*EMB];
__device__ float g_P[SPAN*DIM];
__device__ float g_pre2[NR*DIM];     /* split-K partial scratch / pre2 */

/* FRAG16: block = 16 rows x 16 k = 256 halves. Granule (16B) at (srow,t4)
 * holds m16n8k16 A-quad: {(r,kl),(r,kl+1)},{(r+8,kl),..},{(r,kl+8),..},{(r+8,kl+8),..} */
__device__ __forceinline__ size_t frag16_addr(int r, int k, int ld) {
    size_t blk = (size_t)((r >> 4) * (ld >> 4) + (k >> 4));
    int kk = k & 15;
    return (blk << 8) + (((r & 7) << 2) + ((kk >> 1) & 3)) * 8
         + ((((r >> 3) & 1) + ((kk >> 3) << 1)) << 1) + (kk & 1);
}

__device__ __forceinline__ float gelu_exact(float x) {
    return 0.5f * x * (1.0f + erff(x * 0.70710678118654752440f));
}
__device__ __forceinline__ __half h16(float x) { return __float2half_rn(x); }

__device__ __forceinline__ void mma_f16_16n8k16(float* c, const uint32_t* a,
                                                uint32_t b0, uint32_t b1) {
    asm volatile(
        "mma.sync.aligned.m16n8k16.row.col.f32.f16.f16.f32 "
        "{%0,%1,%2,%3}, {%4,%5,%6,%7}, {%8,%9}, {%0,%1,%2,%3};"
        : "+f"(c[0]), "+f"(c[1]), "+f"(c[2]), "+f"(c[3])
        : "r"(a[0]), "r"(a[1]), "r"(a[2]), "r"(a[3]), "r"(b0), "r"(b1));
}

__device__ __forceinline__ uint32_t smem_u32(const void* p) {
    uint32_t a;
    asm("{ .reg .u64 t; cvta.to.shared.u64 t, %1; cvt.u32.u64 %0, t; }" : "=r"(a) : "l"(p));
    return a;
}

/* =================== fp16 mma.sync GEMM (FRAG16, 3-stage cp.async) =========
 * KC = compile-time K per split slice (mult of 32). NK = KC/32.
 * C[M,Nvalid] = A[M,KC]@Bt[N,KC]^T (+bias); split-K offset via blockIdx.z.
 * CTA 128x128, 128 thr, 4 warps (64x64 warp tile). Stage 16KB x3; 2 CTAs/SM.
 */
template<int KC>
__global__ void __launch_bounds__(128, 2)
mgemm16(const __half* __restrict__ A, int lda,
        const __half* __restrict__ Bt, int ldb, int Nvalid,
        float* __restrict__ C, int ldc,
        const float* __restrict__ bias, int czstride) {
    constexpr int NK = KC >> 5;
    extern __shared__ __align__(16) __half sm16[];
    __half* As = sm16;              /* [3][4096] */
    __half* Bs = sm16 + 3*4096;
    const uint32_t sbA = smem_u32(As);
    const uint32_t sbB = smem_u32(Bs);

    const int tid  = threadIdx.x;
    const int lane = tid & 31;
    const int wid  = tid >> 5;
    const int wr   = (wid & 1) * 64;
    const int wc   = (wid >> 1) * 64;
    const int wrS  = (wid & 1) * 4;
    const int wcS  = (wid >> 1) * 4;
    const int g8   = lane >> 2;
    const int t4   = lane & 3;

    const int mBase = blockIdx.y * 128;
    const int nBase = blockIdx.x * 128;
    const int mSlab = mBase >> 4;
    const int nSlab = nBase >> 4;
    const int k0    = blockIdx.z * KC;
    C += (size_t)blockIdx.z * czstride;
    const int ldaB = lda >> 4;
    const int ldbB = ldb >> 4;

    float acc[4][8][4];
    #pragma unroll
    for (int i = 0; i < 4; i++)
        #pragma unroll
        for (int j = 0; j < 8; j++)
            #pragma unroll
            for (int q = 0; q < 4; q++) acc[i][j][q] = 0.f;

    auto loadA = [&](int s, int kt) {
        const int kbase = (k0 >> 4) + kt*2;
        #pragma unroll
        for (int i = 0; i < 4; i++) {
            int idx  = tid + i*128;
            int slab = idx >> 6;
            int kb   = (idx >> 5) & 1;
            int g    = idx & 31;
            const __half* src = A + (((size_t)(mSlab + slab)*ldaB + (kbase + kb)) << 8) + g*8;
            uint32_t d = sbA + (uint32_t)(s*4096 + ((slab << 1) + kb)*256 + g*8)*2u;
            asm volatile("cp.async.cg.shared.global [%0], [%1], 16;" :: "r"(d), "l"(src));
        }
    };
    auto loadB = [&](int s, int kt) {
        const int kbase = (k0 >> 4) + kt*2;
        #pragma unroll
        for (int i = 0; i < 4; i++) {
            int idx  = tid + i*128;
            int slab = idx >> 6;
            int kb   = (idx >> 5) & 1;
            int g    = idx & 31;
            const __half* src = Bt + (((size_t)(nSlab + slab)*ldbB + (kbase + kb)) << 8) + g*8;
            uint32_t d = sbB + (uint32_t)(s*4096 + ((slab << 1) + kb)*256 + g*8)*2u;
            asm volatile("cp.async.cg.shared.global [%0], [%1], 16;" :: "r"(d), "l"(src));
        }
    };

    loadA(0, 0); loadB(0, 0);
    asm volatile("cp.async.commit_group;");
    if (NK > 1) {
        loadA(1, 1); loadB(1, 1);
        asm volatile("cp.async.commit_group;");
    }

    const int lo = ((g8 << 2) + t4) * 8;

    auto compute_tile = [&](int sc) {
        const __half* as = As + sc*4096;
        const __half* bs = Bs + sc*4096;
        #pragma unroll
        for (int kb = 0; kb < 2; kb++) {
            uint4 aq[4], bq[4];
            #pragma unroll
            for (int mt = 0; mt < 4; mt++)
                aq[mt] = *(const uint4*)(as + (((wrS + mt) << 1) + kb)*256 + lo);
            #pragma unroll
            for (int p = 0; p < 4; p++)
                bq[p] = *(const uint4*)(bs + (((wcS + p) << 1) + kb)*256 + lo);
            #pragma unroll
            for (int mt = 0; mt < 4; mt++) {
                #pragma unroll
                for (int p = 0; p < 4; p++) {
                    mma_f16_16n8k16(acc[mt][2*p],   (const uint32_t*)&aq[mt], bq[p].x, bq[p].z);
                    mma_f16_16n8k16(acc[mt][2*p+1], (const uint32_t*)&aq[mt], bq[p].y, bq[p].w);
                }
            }
        }
    };

    if (NK <= 8) {
        /* fully unrolled pipeline: all stage indices constant-folded */
        #pragma unroll
        for (int kt = 0; kt < NK; kt++) {
            if (kt + 1 < NK)
                asm volatile("cp.async.wait_group 1;");
            else
                asm volatile("cp.async.wait_group 0;");
            __syncthreads();
            if (kt + 2 < NK) {
                loadA((kt + 2) % 3, kt + 2); loadB((kt + 2) % 3, kt + 2);
                asm volatile("cp.async.commit_group;");
            }
            compute_tile(kt % 3);
            __syncthreads();
        }
    } else {
        int sc = 0;
        #pragma unroll 3
        for (int kt = 0; kt < NK; kt++) {
            if (kt + 1 < NK)
                asm volatile("cp.async.wait_group 1;");
            else
                asm volatile("cp.async.wait_group 0;");
            __syncthreads();
            if (kt + 2 < NK) {
                int sn = sc + 2; if (sn >= 3) sn -= 3;
                loadA(sn, kt + 2); loadB(sn, kt + 2);
                asm volatile("cp.async.commit_group;");
            }
            compute_tile(sc);
            __syncthreads();
            if (++sc == 3) sc = 0;
        }
    }

    /* epilogue: plain fp32 C */
    #pragma unroll
    for (int mt = 0; mt < 4; mt++) {
        int r0 = mBase + wr + mt*16 + g8;
        #pragma unroll
        for (int nt = 0; nt < 8; nt++) {
            int cc = nBase + wc + nt*8 + t4*2;
            if (cc < Nvalid) {
                float bx = bias ? bias[cc]   : 0.f;
                float by = bias ? bias[cc+1] : 0.f;
                float2 v0 = make_float2(acc[mt][nt][0] + bx, acc[mt][nt][1] + by);
                float2 v1 = make_float2(acc[mt][nt][2] + bx, acc[mt][nt][3] + by);
                *(float2*)(C + (size_t)r0*ldc + cc)     = v0;
                *(float2*)(C + (size_t)(r0+8)*ldc + cc) = v1;
            }
        }
    }
}

/* =================== producers (write FRAG16 fp16) =================== */
/* vectorized gather: block 192 thr, each handles 4 consecutive k per side */
__global__ void k_gather(const float* __restrict__ hs, const int* __restrict__ pairs) {
    int p = blockIdx.x;
    int l0 = pairs[p*2 + 0];
    int r0 = pairs[p*2 + 1];
    int b  = p / NP;
    const float* hl = hs + ((size_t)b*SEQ + l0)*DIM;
    const float* hr = hs + ((size_t)b*SEQ + r0)*DIM;
    int k = threadIdx.x * 4;                 /* 192 threads * 4 = 768 */
    float4 vl = *(const float4*)(hl + k);
    float4 vr = *(const float4*)(hr + k);
    __half2 l01 = __floats2half2_rn(vl.x, vl.y);
    __half2 l23 = __floats2half2_rn(vl.z, vl.w);
    __half2 r01 = __floats2half2_rn(vr.x, vr.y);
    __half2 r23 = __floats2half2_rn(vr.z, vr.w);
    /* (p,k) and (p,k+1) are adjacent halves; (p,k+2) starts 8 halves later */
    size_t aL = frag16_addr(p, k, K1);
    size_t aR = frag16_addr(p, DIM + k, K1);
    *(__half2*)(g_lr + aL)     = l01;
    *(__half2*)(g_lr + aL + 8) = l23;
    *(__half2*)(g_lr + aR)     = r01;
    *(__half2*)(g_lr + aR + 8) = r23;
}

/* P[l] = pos_emb[l] @ W1[1536:1736] + b1 ; grid (SPAN, 6), block 128 */
__global__ void k_posproj(const float* __restrict__ pos, const float* __restrict__ W1,
                          const float* __restrict__ b1) {
    __shared__ float sp[PE];
    int l = blockIdx.x;
    for (int t = threadIdx.x; t < PE; t += blockDim.x) sp[t] = pos[l*PE + t];
    __syncthreads();
    int j = blockIdx.y * 128 + threadIdx.x;
    float acc = b1[j];
    const float* w = W1 + (size_t)K1*DIM + j;
    #pragma unroll 8
    for (int t = 0; t < PE; t++) acc += sp[t] * w[(size_t)t*DIM];
    g_P[l*DIM + j] = acc;
}

/* transpose + fp16 round -> FRAG16 */
__global__ void k_transpose(const float* __restrict__ in, __half* __restrict__ out, int R, int C) {
    __shared__ float t[32][33];
    int c0 = blockIdx.x*32, r0 = blockIdx.y*32;
    for (int dy = threadIdx.y; dy < 32; dy += 8)
        t[dy][threadIdx.x] = in[(size_t)(r0+dy)*C + c0 + threadIdx.x];
    __syncthreads();
    for (int dy = threadIdx.y; dy < 32; dy += 8)
        out[frag16_addr(c0 + dy, r0 + threadIdx.x, R)] = h16(t[threadIdx.x][dy]);
}

/* Wdec -> FRAG16 g_Wd, granule-wise, zero pad rows */
__global__ void k_cvtWd(const float* __restrict__ in) {
    int gid = blockIdx.x*256 + threadIdx.x;
    int blk = gid >> 5;
    int g   = gid & 31;
    int srow = g >> 2, t4 = g & 3;
    int R0 = (blk >> 3) << 4;
    int K0 = (blk & 7) << 4;
    int r0 = R0 + srow, r1 = r0 + 8;
    int kl = K0 + 2*t4, kh = kl + 8;
    float2 a0 = make_float2(0.f,0.f), a1 = a0, a2 = a0, a3 = a0;
    if (r0 < VOCAB) { a0 = *(const float2*)(in + (size_t)r0*EMB + kl);
                      a2 = *(const float2*)(in + (size_t)r0*EMB + kh); }
    if (r1 < VOCAB) { a1 = *(const float2*)(in + (size_t)r1*EMB + kl);
                      a3 = *(const float2*)(in + (size_t)r1*EMB + kh); }
    __half2 h0 = __floats2half2_rn(a0.x, a0.y);
    __half2 h1 = __floats2half2_rn(a1.x, a1.y);
    __half2 h2 = __floats2half2_rn(a2.x, a2.y);
    __half2 h3 = __floats2half2_rn(a3.x, a3.y);
    uint4 u = make_uint4(*(uint32_t*)&h0, *(uint32_t*)&h1, *(uint32_t*)&h2, *(uint32_t*)&h3);
    *(uint4*)(g_Wd + ((size_t)blk << 8) + (size_t)g*8) = u;
}

/* reduce 4 split-K partials + bias -> g_h3 (FRAG16) */
__global__ void k_reduceh3(const float* __restrict__ part, const float* __restrict__ bp) {
    int i = blockIdx.x*blockDim.x + threadIdx.x;
    float s = bp[i & (EMB-1)];
    #pragma unroll
    for (int z = 0; z < 4; z++) s += part[(size_t)z*(NR*EMB) + i];
    g_h3[frag16_addr(i >> 7, i & 127, EMB)] = h16(s);
}

__device__ __forceinline__ void block_reduce2(float& s, float& sq) {
    __shared__ float ss[8], ssq[8];
    #pragma unroll
    for (int o = 16; o > 0; o >>= 1) {
        s  += __shfl_xor_sync(0xffffffffu, s,  o);
        sq += __shfl_xor_sync(0xffffffffu, sq, o);
    }
    int w = threadIdx.x >> 5;
    if ((threadIdx.x & 31) == 0) { ss[w] = s; ssq[w] = sq; }
    __syncthreads();
    s = 0.f; sq = 0.f;
    #pragma unroll
    for (int i = 0; i < 8; i++) { s += ss[i]; sq += ssq[i]; }
}

/* h1 = LN(gelu(sum_z Apart[z] + P[l])) ; reads 8 split-K partials directly */
__global__ void k_fuse1(const float* __restrict__ part,
                        const float* __restrict__ g1, const float* __restrict__ be1) {
    int r = blockIdx.x;
    int p = r / SPAN, l = r % SPAN;
    const float* Pl = g_P + (size_t)l*DIM;
    float v[3];
    float s = 0.f, sq = 0.f;
    int j0 = threadIdx.x;
    #pragma unroll
    for (int t = 0; t < 3; t++) {
        int j = j0 + t*256;
        float a = Pl[j];
        #pragma unroll
        for (int z = 0; z < 8; z++) a += part[(size_t)z*(NB*DIM) + (size_t)p*DIM + j];
        float x = gelu_exact(a);
        v[t] = x; s += x; sq += x*x;
    }
    block_reduce2(s, sq);
    float mean = s * (1.0f/DIM);
    float var  = sq * (1.0f/DIM) - mean*mean;
    float rstd = rsqrtf(var + 1e-12f);
    #pragma unroll
    for (int t = 0; t < 3; t++) {
        int j = j0 + t*256;
        g_h1[frag16_addr(r, j, DIM)] = h16((v[t] - mean) * rstd * g1[j] + be1[j]);
    }
}

__global__ void k_gelu_ln(const float* __restrict__ in,
                          const float* __restrict__ g, const float* __restrict__ be) {
    int r = blockIdx.x;
    const float* ip = in + (size_t)r*DIM;
    float v[3];
    float s = 0.f, sq = 0.f;
    int j0 = threadIdx.x;
    #pragma unroll
    for (int t = 0; t < 3; t++) {
        int j = j0 + t*256;
        float x = gelu_exact(ip[j]);
        v[t] = x; s += x; sq += x*x;
    }
    block_reduce2(s, sq);
    float mean = s * (1.0f/DIM);
    float var  = sq * (1.0f/DIM) - mean*mean;
    float rstd = rsqrtf(var + 1e-12f);
    #pragma unroll
    for (int t = 0; t < 3; t++) {
        int j = j0 + t*256;
        g_h2[frag16_addr(r, j, DIM)] = h16((v[t] - mean) * rstd * g[j] + be[j]);
    }
}

/* ---------------- host launch ---------------- */
extern "C" void kernel_launch(void* const* d_in, const int* in_sizes, int n_in,
                              void* d_out, int out_size) {
    const float* hs    = (const float*)d_in[0];
    const int*   pairs = (const int*)  d_in[1];
    const float* pos   = (const float*)d_in[2];
    const float* W1    = (const float*)d_in[3];
    const float* b1    = (const float*)d_in[4];
    const float* g1    = (const float*)d_in[5];
    const float* be1   = (const float*)d_in[6];
    const float* W2    = (const float*)d_in[7];
    const float* b2    = (const float*)d_in[8];
    const float* g2    = (const float*)d_in[9];
    const float* be2   = (const float*)d_in[10];
    const float* Wp    = (const float*)d_in[11];
    const float* bp    = (const float*)d_in[12];
    const float* Wdec  = (const float*)d_in[13];
    float* out = (float*)d_out;
    (void)in_sizes; (void)n_in; (void)out_size;

    __half *p_lr, *p_h1, *p_h2, *p_h3, *p_W1T, *p_W2T, *p_WpT, *p_Wd;
    float *p_pre2;
    cudaGetSymbolAddress((void**)&p_lr,   g_lr);
    cudaGetSymbolAddress((void**)&p_h1,   g_h1);
    cudaGetSymbolAddress((void**)&p_h2,   g_h2);
    cudaGetSymbolAddress((void**)&p_h3,   g_h3);
    cudaGetSymbolAddress((void**)&p_W1T,  g_W1T);
    cudaGetSymbolAddress((void**)&p_W2T,  g_W2T);
    cudaGetSymbolAddress((void**)&p_WpT,  g_WpT);
    cudaGetSymbolAddress((void**)&p_Wd,   g_Wd);
    cudaGetSymbolAddress((void**)&p_pre2, g_pre2);

    const int MSMEM = 6 * 4096 * 2;   /* 3 stages x (A+B) = 49152 B */
    cudaFuncSetAttribute(mgemm16<192>, cudaFuncAttributeMaxDynamicSharedMemorySize, MSMEM);
    cudaFuncSetAttribute(mgemm16<768>, cudaFuncAttributeMaxDynamicSharedMemorySize, MSMEM);
    cudaFuncSetAttribute(mgemm16<128>, cudaFuncAttributeMaxDynamicSharedMemorySize, MSMEM);

    /* 0) fp16 rounding into FRAG16 */
    k_transpose<<<dim3(DIM/32, K1/32), dim3(32,8)>>>(W1, p_W1T, K1, DIM);
    k_transpose<<<dim3(DIM/32, DIM/32), dim3(32,8)>>>(W2, p_W2T, DIM, DIM);
    k_transpose<<<dim3(EMB/32, DIM/32), dim3(32,8)>>>(Wp, p_WpT, DIM, EMB);
    k_cvtWd<<<(VROWS*EMB/8)/256, 256>>>(Wdec);

    /* 1) gather [lh, rh] rows */
    k_gather<<<NB, 192>>>(hs, pairs);

    /* 2) P = pos_emb @ W1c + b1 */
    k_posproj<<<dim3(SPAN, DIM/128), 128>>>(pos, W1, b1);

    /* 3) A-partials = g_lr @ W1[0:1536]  split-K x8 (into g_pre2) */
    mgemm16<192><<<dim3(DIM/128, NB/128, 8), 128, MSMEM>>>(
        p_lr, K1, p_W1T, K1, DIM, p_pre2, DIM, nullptr, NB*DIM);

    /* 4) h1 = LN(gelu(sum partials + P)) -> FRAG16 (reduce fused) */
    k_fuse1<<<NR, 256>>>(p_pre2, g1, be1);

    /* 5) pre2 = h1 @ W2 + b2 ; h2 = LN(gelu(pre2)) -> FRAG16 */
    mgemm16<768><<<dim3(DIM/128, NR/128, 1), 128, MSMEM>>>(
        p_h1, DIM, p_W2T, DIM, DIM, p_pre2, DIM, b2, 0);
    k_gelu_ln<<<NR, 256>>>(p_pre2, g2, be2);

    /* 6) h3 = h2 @ Wp + bp  split-K x4 -> FRAG16 via reduce */
    mgemm16<192><<<dim3(EMB/128, NR/128, 4), 128, MSMEM>>>(
        p_h2, DIM, p_WpT, DIM, EMB, p_pre2, EMB, nullptr, NR*EMB);
    k_reduceh3<<<(NR*EMB)/256, 256>>>(p_pre2, bp);

    /* 7) out = h3 @ Wd^T (M=5120 N=30522(+pad) K=128) */
    mgemm16<128><<<dim3(VROWS/128, NR/128, 1), 128, MSMEM>>>(
        p_h3, EMB, p_Wd, EMB, VOCAB, out, VOCAB, nullptr, 0);
}

// round 11
// speedup vs baseline: 1.9680x; 1.0518x over previous
#include <cuda_runtime.h>
#include <cuda_fp16.h>
#include <math.h>
#include <stdint.h>

#define BSZ   8
#define SEQ   512
#define DIM   768
#define NP    32
#define PE    200
#define EMB   128
#define VOCAB 30522
#define SPAN  20
#define NB    (BSZ*NP)        /* 256 span pairs */
#define NR    (NB*SPAN)       /* 5120 rows */
#define K1    1536            /* 2*DIM */
#define VROWS 30592           /* 239*128, padded vocab rows */

/* ---------------- scratch (no allocation allowed) ---------------- */
__device__ __align__(256) __half g_lr[NB*K1];
__device__ __align__(256) __half g_h1[NR*DIM];
__device__ __align__(256) __half g_h2[NR*DIM];
__device__ __align__(256) __half g_h3[NR*EMB];
__device__ __align__(256) __half g_W1T[DIM*K1];
__device__ __align__(256) __half g_W2T[DIM*DIM];
__device__ __align__(256) __half g_WpT[EMB*DIM];
__device__ __align__(256) __half g_Wd[VROWS*EMB];
__device__ float g_P[SPAN*DIM];
__device__ float g_pre2[NR*DIM];     /* split-K partial scratch / pre2 */

/* FRAG16: block = 16 rows x 16 k = 256 halves. Granule (16B) at (srow,t4)
 * holds m16n8k16 A-quad. For fixed r and k%4==0: (r,k),(r,k+1) adjacent
 * halves; (r,k+2),(r,k+3) at +8 halves. */
__device__ __forceinline__ size_t frag16_addr(int r, int k, int ld) {
    size_t blk = (size_t)((r >> 4) * (ld >> 4) + (k >> 4));
    int kk = k & 15;
    return (blk << 8) + (((r & 7) << 2) + ((kk >> 1) & 3)) * 8
         + ((((r >> 3) & 1) + ((kk >> 3) << 1)) << 1) + (kk & 1);
}

__device__ __forceinline__ float gelu_exact(float x) {
    return 0.5f * x * (1.0f + erff(x * 0.70710678118654752440f));
}
__device__ __forceinline__ __half h16(float x) { return __float2half_rn(x); }

__device__ __forceinline__ void mma_f16_16n8k16(float* c, const uint32_t* a,
                                                uint32_t b0, uint32_t b1) {
    asm volatile(
        "mma.sync.aligned.m16n8k16.row.col.f32.f16.f16.f32 "
        "{%0,%1,%2,%3}, {%4,%5,%6,%7}, {%8,%9}, {%0,%1,%2,%3};"
        : "+f"(c[0]), "+f"(c[1]), "+f"(c[2]), "+f"(c[3])
        : "r"(a[0]), "r"(a[1]), "r"(a[2]), "r"(a[3]), "r"(b0), "r"(b1));
}

__device__ __forceinline__ uint32_t smem_u32(const void* p) {
    uint32_t a;
    asm("{ .reg .u64 t; cvta.to.shared.u64 t, %1; cvt.u32.u64 %0, t; }" : "=r"(a) : "l"(p));
    return a;
}

/* =================== fp16 mma.sync GEMM (FRAG16, 3-stage cp.async) ========= */
template<int KC>
__global__ void __launch_bounds__(128, 2)
mgemm16(const __half* __restrict__ A, int lda,
        const __half* __restrict__ Bt, int ldb, int Nvalid,
        float* __restrict__ C, int ldc,
        const float* __restrict__ bias, int czstride) {
    constexpr int NK = KC >> 5;
    extern __shared__ __align__(16) __half sm16[];
    __half* As = sm16;              /* [3][4096] */
    __half* Bs = sm16 + 3*4096;
    const uint32_t sbA = smem_u32(As);
    const uint32_t sbB = smem_u32(Bs);

    const int tid  = threadIdx.x;
    const int lane = tid & 31;
    const int wid  = tid >> 5;
    const int wr   = (wid & 1) * 64;
    const int wc   = (wid >> 1) * 64;
    const int wrS  = (wid & 1) * 4;
    const int wcS  = (wid >> 1) * 4;
    const int g8   = lane >> 2;
    const int t4   = lane & 3;

    const int mBase = blockIdx.y * 128;
    const int nBase = blockIdx.x * 128;
    const int mSlab = mBase >> 4;
    const int nSlab = nBase >> 4;
    const int k0    = blockIdx.z * KC;
    C += (size_t)blockIdx.z * czstride;
    const int ldaB = lda >> 4;
    const int ldbB = ldb >> 4;

    float acc[4][8][4];
    #pragma unroll
    for (int i = 0; i < 4; i++)
        #pragma unroll
        for (int j = 0; j < 8; j++)
            #pragma unroll
            for (int q = 0; q < 4; q++) acc[i][j][q] = 0.f;

    auto loadA = [&](int s, int kt) {
        const int kbase = (k0 >> 4) + kt*2;
        #pragma unroll
        for (int i = 0; i < 4; i++) {
            int idx  = tid + i*128;
            int slab = idx >> 6;
            int kb   = (idx >> 5) & 1;
            int g    = idx & 31;
            const __half* src = A + (((size_t)(mSlab + slab)*ldaB + (kbase + kb)) << 8) + g*8;
            uint32_t d = sbA + (uint32_t)(s*4096 + ((slab << 1) + kb)*256 + g*8)*2u;
            asm volatile("cp.async.cg.shared.global [%0], [%1], 16;" :: "r"(d), "l"(src));
        }
    };
    auto loadB = [&](int s, int kt) {
        const int kbase = (k0 >> 4) + kt*2;
        #pragma unroll
        for (int i = 0; i < 4; i++) {
            int idx  = tid + i*128;
            int slab = idx >> 6;
            int kb   = (idx >> 5) & 1;
            int g    = idx & 31;
            const __half* src = Bt + (((size_t)(nSlab + slab)*ldbB + (kbase + kb)) << 8) + g*8;
            uint32_t d = sbB + (uint32_t)(s*4096 + ((slab << 1) + kb)*256 + g*8)*2u;
            asm volatile("cp.async.cg.shared.global [%0], [%1], 16;" :: "r"(d), "l"(src));
        }
    };

    loadA(0, 0); loadB(0, 0);
    asm volatile("cp.async.commit_group;");
    if (NK > 1) {
        loadA(1, 1); loadB(1, 1);
        asm volatile("cp.async.commit_group;");
    }

    const int lo = ((g8 << 2) + t4) * 8;

    auto compute_tile = [&](int sc) {
        const __half* as = As + sc*4096;
        const __half* bs = Bs + sc*4096;
        #pragma unroll
        for (int kb = 0; kb < 2; kb++) {
            uint4 aq[4], bq[4];
            #pragma unroll
            for (int mt = 0; mt < 4; mt++)
                aq[mt] = *(const uint4*)(as + (((wrS + mt) << 1) + kb)*256 + lo);
            #pragma unroll
            for (int p = 0; p < 4; p++)
                bq[p] = *(const uint4*)(bs + (((wcS + p) << 1) + kb)*256 + lo);
            #pragma unroll
            for (int mt = 0; mt < 4; mt++) {
                #pragma unroll
                for (int p = 0; p < 4; p++) {
                    mma_f16_16n8k16(acc[mt][2*p],   (const uint32_t*)&aq[mt], bq[p].x, bq[p].z);
                    mma_f16_16n8k16(acc[mt][2*p+1], (const uint32_t*)&aq[mt], bq[p].y, bq[p].w);
                }
            }
        }
    };

    if (NK <= 8) {
        #pragma unroll
        for (int kt = 0; kt < NK; kt++) {
            if (kt + 1 < NK)
                asm volatile("cp.async.wait_group 1;");
            else
                asm volatile("cp.async.wait_group 0;");
            __syncthreads();
            if (kt + 2 < NK) {
                loadA((kt + 2) % 3, kt + 2); loadB((kt + 2) % 3, kt + 2);
                asm volatile("cp.async.commit_group;");
            }
            compute_tile(kt % 3);
            __syncthreads();
        }
    } else {
        int sc = 0;
        #pragma unroll 3
        for (int kt = 0; kt < NK; kt++) {
            if (kt + 1 < NK)
                asm volatile("cp.async.wait_group 1;");
            else
                asm volatile("cp.async.wait_group 0;");
            __syncthreads();
            if (kt + 2 < NK) {
                int sn = sc + 2; if (sn >= 3) sn -= 3;
                loadA(sn, kt + 2); loadB(sn, kt + 2);
                asm volatile("cp.async.commit_group;");
            }
            compute_tile(sc);
            __syncthreads();
            if (++sc == 3) sc = 0;
        }
    }

    #pragma unroll
    for (int mt = 0; mt < 4; mt++) {
        int r0 = mBase + wr + mt*16 + g8;
        #pragma unroll
        for (int nt = 0; nt < 8; nt++) {
            int cc = nBase + wc + nt*8 + t4*2;
            if (cc < Nvalid) {
                float bx = bias ? bias[cc]   : 0.f;
                float by = bias ? bias[cc+1] : 0.f;
                float2 v0 = make_float2(acc[mt][nt][0] + bx, acc[mt][nt][1] + by);
                float2 v1 = make_float2(acc[mt][nt][2] + bx, acc[mt][nt][3] + by);
                *(float2*)(C + (size_t)r0*ldc + cc)     = v0;
                *(float2*)(C + (size_t)(r0+8)*ldc + cc) = v1;
            }
        }
    }
}

/* =================== fused producer kernel ===================
 * flat grid, 256 threads:
 *  [0,1152)     transpose W1 -> g_W1T    (24 x 48 tiles of 32x32)
 *  [1152,1728)  transpose W2 -> g_W2T    (24 x 24)
 *  [1728,1824)  transpose Wp -> g_WpT    (4 x 24)
 *  [1824,3736)  Wdec -> g_Wd (FRAG16 granules, zero pad)
 *  [3736,3992)  gather lh/rh -> g_lr
 *  [3992,4052)  posproj -> g_P  (SPAN x 3 chunks of 256 cols)
 */
#define PREP_GRID 4052
__global__ void __launch_bounds__(256) k_prep(
    const float* __restrict__ hs, const int* __restrict__ pairs,
    const float* __restrict__ pos, const float* __restrict__ W1,
    const float* __restrict__ b1, const float* __restrict__ W2,
    const float* __restrict__ Wp, const float* __restrict__ Wdec) {
    __shared__ float smem_t[32*33];   /* transpose tile / posproj sp */
    const int bx  = blockIdx.x;
    const int tid = threadIdx.x;

    if (bx < 1824) {
        const float* in; __half* out; int R, C, l, gx;
        if (bx < 1152)      { in = W1; out = g_W1T; R = K1;  C = DIM; l = bx;        gx = 24; }
        else if (bx < 1728) { in = W2; out = g_W2T; R = DIM; C = DIM; l = bx - 1152; gx = 24; }
        else                { in = Wp; out = g_WpT; R = DIM; C = EMB; l = bx - 1728; gx = 4;  }
        int c0 = (l % gx) * 32, r0 = (l / gx) * 32;
        int tx = tid & 31, ty = tid >> 5;
        float (*t)[33] = (float(*)[33])smem_t;
        #pragma unroll
        for (int dy = ty; dy < 32; dy += 8)
            t[dy][tx] = in[(size_t)(r0 + dy)*C + c0 + tx];
        __syncthreads();
        #pragma unroll
        for (int dy = ty; dy < 32; dy += 8)
            out[frag16_addr(c0 + dy, r0 + tx, R)] = h16(t[tx][dy]);
    } else if (bx < 3736) {
        int gid = (bx - 1824)*256 + tid;
        int blk = gid >> 5;
        int g   = gid & 31;
        int srow = g >> 2, t4 = g & 3;
        int R0 = (blk >> 3) << 4;
        int K0 = (blk & 7) << 4;
        int r0 = R0 + srow, r1 = r0 + 8;
        int kl = K0 + 2*t4, kh = kl + 8;
        float2 a0 = make_float2(0.f,0.f), a1 = a0, a2 = a0, a3 = a0;
        if (r0 < VOCAB) { a0 = *(const float2*)(Wdec + (size_t)r0*EMB + kl);
                          a2 = *(const float2*)(Wdec + (size_t)r0*EMB + kh); }
        if (r1 < VOCAB) { a1 = *(const float2*)(Wdec + (size_t)r1*EMB + kl);
                          a3 = *(const float2*)(Wdec + (size_t)r1*EMB + kh); }
        __half2 h0 = __floats2half2_rn(a0.x, a0.y);
        __half2 h1 = __floats2half2_rn(a1.x, a1.y);
        __half2 h2 = __floats2half2_rn(a2.x, a2.y);
        __half2 h3 = __floats2half2_rn(a3.x, a3.y);
        uint4 u = make_uint4(*(uint32_t*)&h0, *(uint32_t*)&h1, *(uint32_t*)&h2, *(uint32_t*)&h3);
        *(uint4*)(g_Wd + ((size_t)blk << 8) + (size_t)g*8) = u;
    } else if (bx < 3992) {
        if (tid < 192) {
            int p = bx - 3736;
            int l0 = pairs[p*2 + 0];
            int r0 = pairs[p*2 + 1];
            int b  = p / NP;
            const float* hl = hs + ((size_t)b*SEQ + l0)*DIM;
            const float* hr = hs + ((size_t)b*SEQ + r0)*DIM;
            int k = tid * 4;
            float4 vl = *(const float4*)(hl + k);
            float4 vr = *(const float4*)(hr + k);
            __half2 l01 = __floats2half2_rn(vl.x, vl.y);
            __half2 l23 = __floats2half2_rn(vl.z, vl.w);
            __half2 r01 = __floats2half2_rn(vr.x, vr.y);
            __half2 r23 = __floats2half2_rn(vr.z, vr.w);
            size_t aL = frag16_addr(p, k, K1);
            size_t aR = frag16_addr(p, DIM + k, K1);
            *(__half2*)(g_lr + aL)     = l01;
            *(__half2*)(g_lr + aL + 8) = l23;
            *(__half2*)(g_lr + aR)     = r01;
            *(__half2*)(g_lr + aR + 8) = r23;
        }
    } else {
        int loc = bx - 3992;
        int l = loc / 3, sub = loc % 3;
        float* sp = smem_t;
        for (int t2 = tid; t2 < PE; t2 += 256) sp[t2] = pos[l*PE + t2];
        __syncthreads();
        int j = sub*256 + tid;
        float acc = b1[j];
        const float* w = W1 + (size_t)K1*DIM + j;
        #pragma unroll 8
        for (int t2 = 0; t2 < PE; t2++) acc += sp[t2] * w[(size_t)t2*DIM];
        g_P[l*DIM + j] = acc;
    }
}

/* =================== LN kernels: 192 thr x 4 consecutive j =============== */
__device__ __forceinline__ void block_reduce2_192(float& s, float& sq) {
    __shared__ float ss[6], ssq[6];
    #pragma unroll
    for (int o = 16; o > 0; o >>= 1) {
        s  += __shfl_xor_sync(0xffffffffu, s,  o);
        sq += __shfl_xor_sync(0xffffffffu, sq, o);
    }
    int w = threadIdx.x >> 5;
    if ((threadIdx.x & 31) == 0) { ss[w] = s; ssq[w] = sq; }
    __syncthreads();
    s = 0.f; sq = 0.f;
    #pragma unroll
    for (int i = 0; i < 6; i++) { s += ss[i]; sq += ssq[i]; }
}

/* h1 = LN(gelu(sum_z Apart[z] + P[l])) -> FRAG16, vectorized */
__global__ void __launch_bounds__(192) k_fuse1(const float* __restrict__ part,
                        const float* __restrict__ g1, const float* __restrict__ be1) {
    int r = blockIdx.x;
    int p = r / SPAN, l = r % SPAN;
    int j = threadIdx.x * 4;
    float4 a4 = *(const float4*)(g_P + (size_t)l*DIM + j);
    float a[4] = {a4.x, a4.y, a4.z, a4.w};
    #pragma unroll
    for (int z = 0; z < 8; z++) {
        float4 pz = *(const float4*)(part + (size_t)z*(NB*DIM) + (size_t)p*DIM + j);
        a[0] += pz.x; a[1] += pz.y; a[2] += pz.z; a[3] += pz.w;
    }
    float v[4];
    float s = 0.f, sq = 0.f;
    #pragma unroll
    for (int q = 0; q < 4; q++) {
        v[q] = gelu_exact(a[q]); s += v[q]; sq += v[q]*v[q];
    }
    block_reduce2_192(s, sq);
    float mean = s * (1.0f/DIM);
    float var  = sq * (1.0f/DIM) - mean*mean;
    float rstd = rsqrtf(var + 1e-12f);
    float4 gg = *(const float4*)(g1 + j);
    float4 bb = *(const float4*)(be1 + j);
    float o0 = (v[0]-mean)*rstd*gg.x + bb.x;
    float o1 = (v[1]-mean)*rstd*gg.y + bb.y;
    float o2 = (v[2]-mean)*rstd*gg.z + bb.z;
    float o3 = (v[3]-mean)*rstd*gg.w + bb.w;
    size_t ad = frag16_addr(r, j, DIM);
    *(__half2*)(g_h1 + ad)     = __floats2half2_rn(o0, o1);
    *(__half2*)(g_h1 + ad + 8) = __floats2half2_rn(o2, o3);
}

/* h2 = LN(gelu(pre2)) -> FRAG16, vectorized */
__global__ void __launch_bounds__(192) k_gelu_ln(const float* __restrict__ in,
                          const float* __restrict__ g, const float* __restrict__ be) {
    int r = blockIdx.x;
    int j = threadIdx.x * 4;
    float4 a4 = *(const float4*)(in + (size_t)r*DIM + j);
    float v[4];
    float s = 0.f, sq = 0.f;
    v[0] = gelu_exact(a4.x); v[1] = gelu_exact(a4.y);
    v[2] = gelu_exact(a4.z); v[3] = gelu_exact(a4.w);
    #pragma unroll
    for (int q = 0; q < 4; q++) { s += v[q]; sq += v[q]*v[q]; }
    block_reduce2_192(s, sq);
    float mean = s * (1.0f/DIM);
    float var  = sq * (1.0f/DIM) - mean*mean;
    float rstd = rsqrtf(var + 1e-12f);
    float4 gg = *(const float4*)(g + j);
    float4 bb = *(const float4*)(be + j);
    float o0 = (v[0]-mean)*rstd*gg.x + bb.x;
    float o1 = (v[1]-mean)*rstd*gg.y + bb.y;
    float o2 = (v[2]-mean)*rstd*gg.z + bb.z;
    float o3 = (v[3]-mean)*rstd*gg.w + bb.w;
    size_t ad = frag16_addr(r, j, DIM);
    *(__half2*)(g_h2 + ad)     = __floats2half2_rn(o0, o1);
    *(__half2*)(g_h2 + ad + 8) = __floats2half2_rn(o2, o3);
}

/* reduce 4 split-K partials + bias -> g_h3 (FRAG16), vectorized */
__global__ void __launch_bounds__(256) k_reduceh3(const float* __restrict__ part,
                                                  const float* __restrict__ bp) {
    int i = (blockIdx.x*256 + threadIdx.x) * 4;
    float4 b4 = *(const float4*)(bp + (i & 127));
    float s0 = b4.x, s1 = b4.y, s2 = b4.z, s3 = b4.w;
    #pragma unroll
    for (int z = 0; z < 4; z++) {
        float4 pz = *(const float4*)(part + (size_t)z*(NR*EMB) + i);
        s0 += pz.x; s1 += pz.y; s2 += pz.z; s3 += pz.w;
    }
    size_t ad = frag16_addr(i >> 7, i & 127, EMB);
    *(__half2*)(g_h3 + ad)     = __floats2half2_rn(s0, s1);
    *(__half2*)(g_h3 + ad + 8) = __floats2half2_rn(s2, s3);
}

/* ---------------- host launch ---------------- */
extern "C" void kernel_launch(void* const* d_in, const int* in_sizes, int n_in,
                              void* d_out, int out_size) {
    const float* hs    = (const float*)d_in[0];
    const int*   pairs = (const int*)  d_in[1];
    const float* pos   = (const float*)d_in[2];
    const float* W1    = (const float*)d_in[3];
    const float* b1    = (const float*)d_in[4];
    const float* g1    = (const float*)d_in[5];
    const float* be1   = (const float*)d_in[6];
    const float* W2    = (const float*)d_in[7];
    const float* b2    = (const float*)d_in[8];
    const float* g2    = (const float*)d_in[9];
    const float* be2   = (const float*)d_in[10];
    const float* Wp    = (const float*)d_in[11];
    const float* bp    = (const float*)d_in[12];
    const float* Wdec  = (const float*)d_in[13];
    float* out = (float*)d_out;
    (void)in_sizes; (void)n_in; (void)out_size;

    __half *p_lr, *p_h1, *p_h2, *p_h3, *p_W1T, *p_W2T, *p_WpT, *p_Wd;
    float *p_pre2;
    cudaGetSymbolAddress((void**)&p_lr,   g_lr);
    cudaGetSymbolAddress((void**)&p_h1,   g_h1);
    cudaGetSymbolAddress((void**)&p_h2,   g_h2);
    cudaGetSymbolAddress((void**)&p_h3,   g_h3);
    cudaGetSymbolAddress((void**)&p_W1T,  g_W1T);
    cudaGetSymbolAddress((void**)&p_W2T,  g_W2T);
    cudaGetSymbolAddress((void**)&p_WpT,  g_WpT);
    cudaGetSymbolAddress((void**)&p_Wd,   g_Wd);
    cudaGetSymbolAddress((void**)&p_pre2, g_pre2);

    const int MSMEM = 6 * 4096 * 2;   /* 49152 B */
    cudaFuncSetAttribute(mgemm16<192>, cudaFuncAttributeMaxDynamicSharedMemorySize, MSMEM);
    cudaFuncSetAttribute(mgemm16<768>, cudaFuncAttributeMaxDynamicSharedMemorySize, MSMEM);
    cudaFuncSetAttribute(mgemm16<128>, cudaFuncAttributeMaxDynamicSharedMemorySize, MSMEM);

    /* 0) one fused producer launch: transposes + Wd + gather + posproj */
    k_prep<<<PREP_GRID, 256>>>(hs, pairs, pos, W1, b1, W2, Wp, Wdec);

    /* 1) A-partials = g_lr @ W1[0:1536]  split-K x8 (into g_pre2) */
    mgemm16<192><<<dim3(DIM/128, NB/128, 8), 128, MSMEM>>>(
        p_lr, K1, p_W1T, K1, DIM, p_pre2, DIM, nullptr, NB*DIM);

    /* 2) h1 = LN(gelu(sum partials + P)) -> FRAG16 */
    k_fuse1<<<NR, 192>>>(p_pre2, g1, be1);

    /* 3) pre2 = h1 @ W2 + b2 ; h2 = LN(gelu(pre2)) -> FRAG16 */
    mgemm16<768><<<dim3(DIM/128, NR/128, 1), 128, MSMEM>>>(
        p_h1, DIM, p_W2T, DIM, DIM, p_pre2, DIM, b2, 0);
    k_gelu_ln<<<NR, 192>>>(p_pre2, g2, be2);

    /* 4) h3 = h2 @ Wp + bp  split-K x4 -> FRAG16 via reduce */
    mgemm16<192><<<dim3(EMB/128, NR/128, 4), 128, MSMEM>>>(
        p_h2, DIM, p_WpT, DIM, EMB, p_pre2, EMB, nullptr, NR*EMB);
    k_reduceh3<<<(NR*EMB)/1024, 256>>>(p_pre2, bp);

    /* 5) out = h3 @ Wd^T (M=5120 N=30522(+pad) K=128) */
    mgemm16<128><<<dim3(VROWS/128, NR/128, 1), 128, MSMEM>>>(
        p_h3, EMB, p_Wd, EMB, VOCAB, out, VOCAB, nullptr, 0);
}

// round 12
// speedup vs baseline: 2.2857x; 1.1615x over previous
#include <cuda_runtime.h>
#include <cuda_fp16.h>
#include <math.h>
#include <stdint.h>

#define BSZ   8
#define SEQ   512
#define DIM   768
#define NP    32
#define PE    200
#define EMB   128
#define VOCAB 30522
#define SPAN  20
#define NB    (BSZ*NP)        /* 256 span pairs */
#define NR    (NB*SPAN)       /* 5120 rows */
#define K1    1536            /* 2*DIM */
#define VROWS 30592           /* 239*128, padded vocab rows */

/* ---------------- scratch (no allocation allowed) ---------------- */
__device__ __align__(256) __half g_lr[NB*K1];
__device__ __align__(256) __half g_h1[NR*DIM];
__device__ __align__(256) __half g_h2[NR*DIM];
__device__ __align__(256) __half g_h3[NR*EMB];
__device__ __align__(256) __half g_W1T[DIM*K1];
__device__ __align__(256) __half g_W2T[DIM*DIM];
__device__ __align__(256) __half g_WpT[EMB*DIM];
__device__ __align__(256) __half g_Wd[VROWS*EMB];
__device__ float g_P[SPAN*DIM];
__device__ float g_pre2[NR*DIM];     /* split-K partial scratch / pre2 */

/* FRAG16: block = 16 rows x 16 k = 256 halves. Granule (16B) at (srow,t4)
 * holds m16n8k16 A-quad. For fixed r and k%4==0: (r,k),(r,k+1) adjacent
 * halves; (r,k+2),(r,k+3) at +8 halves. */
__device__ __forceinline__ size_t frag16_addr(int r, int k, int ld) {
    size_t blk = (size_t)((r >> 4) * (ld >> 4) + (k >> 4));
    int kk = k & 15;
    return (blk << 8) + (((r & 7) << 2) + ((kk >> 1) & 3)) * 8
         + ((((r >> 3) & 1) + ((kk >> 3) << 1)) << 1) + (kk & 1);
}

__device__ __forceinline__ float gelu_exact(float x) {
    return 0.5f * x * (1.0f + erff(x * 0.70710678118654752440f));
}
__device__ __forceinline__ __half h16(float x) { return __float2half_rn(x); }

__device__ __forceinline__ void mma_f16_16n8k16(float* c, const uint32_t* a,
                                                uint32_t b0, uint32_t b1) {
    asm volatile(
        "mma.sync.aligned.m16n8k16.row.col.f32.f16.f16.f32 "
        "{%0,%1,%2,%3}, {%4,%5,%6,%7}, {%8,%9}, {%0,%1,%2,%3};"
        : "+f"(c[0]), "+f"(c[1]), "+f"(c[2]), "+f"(c[3])
        : "r"(a[0]), "r"(a[1]), "r"(a[2]), "r"(a[3]), "r"(b0), "r"(b1));
}

__device__ __forceinline__ uint32_t smem_u32(const void* p) {
    uint32_t a;
    asm("{ .reg .u64 t; cvta.to.shared.u64 t, %1; cvt.u32.u64 %0, t; }" : "=r"(a) : "l"(p));
    return a;
}

/* =================== fp16 mma.sync GEMM (FRAG16, 3-stage cp.async) =========
 * 256 threads / 8 warps, warp tile 64x32 (acc 64 regs) for occupancy:
 * 2 CTAs/SM -> 16 warps/SM. CTA tile 128x128, BK=32.
 */
template<int KC>
__global__ void __launch_bounds__(256, 2)
mgemm16(const __half* __restrict__ A, int lda,
        const __half* __restrict__ Bt, int ldb, int Nvalid,
        float* __restrict__ C, int ldc,
        const float* __restrict__ bias, int czstride) {
    constexpr int NK = KC >> 5;
    extern __shared__ __align__(16) __half sm16[];
    __half* As = sm16;              /* [3][4096] */
    __half* Bs = sm16 + 3*4096;
    const uint32_t sbA = smem_u32(As);
    const uint32_t sbB = smem_u32(Bs);

    const int tid  = threadIdx.x;
    const int lane = tid & 31;
    const int wid  = tid >> 5;
    const int wr   = (wid & 1) * 64;   /* warp rows: 2 groups */
    const int wc   = (wid >> 1) * 32;  /* warp cols: 4 groups */
    const int wrS  = (wid & 1) * 4;    /* row slabs (16 rows)  */
    const int wcS  = (wid >> 1) * 2;   /* col slabs (16 cols)  */
    const int g8   = lane >> 2;
    const int t4   = lane & 3;

    const int mBase = blockIdx.y * 128;
    const int nBase = blockIdx.x * 128;
    const int mSlab = mBase >> 4;
    const int nSlab = nBase >> 4;
    const int k0    = blockIdx.z * KC;
    C += (size_t)blockIdx.z * czstride;
    const int ldaB = lda >> 4;
    const int ldbB = ldb >> 4;

    float acc[4][4][4];
    #pragma unroll
    for (int i = 0; i < 4; i++)
        #pragma unroll
        for (int j = 0; j < 4; j++)
            #pragma unroll
            for (int q = 0; q < 4; q++) acc[i][j][q] = 0.f;

    auto loadA = [&](int s, int kt) {
        const int kbase = (k0 >> 4) + kt*2;
        #pragma unroll
        for (int i = 0; i < 2; i++) {
            int idx  = tid + i*256;
            int slab = idx >> 6;
            int kb   = (idx >> 5) & 1;
            int g    = idx & 31;
            const __half* src = A + (((size_t)(mSlab + slab)*ldaB + (kbase + kb)) << 8) + g*8;
            uint32_t d = sbA + (uint32_t)(s*4096 + ((slab << 1) + kb)*256 + g*8)*2u;
            asm volatile("cp.async.cg.shared.global [%0], [%1], 16;" :: "r"(d), "l"(src));
        }
    };
    auto loadB = [&](int s, int kt) {
        const int kbase = (k0 >> 4) + kt*2;
        #pragma unroll
        for (int i = 0; i < 2; i++) {
            int idx  = tid + i*256;
            int slab = idx >> 6;
            int kb   = (idx >> 5) & 1;
            int g    = idx & 31;
            const __half* src = Bt + (((size_t)(nSlab + slab)*ldbB + (kbase + kb)) << 8) + g*8;
            uint32_t d = sbB + (uint32_t)(s*4096 + ((slab << 1) + kb)*256 + g*8)*2u;
            asm volatile("cp.async.cg.shared.global [%0], [%1], 16;" :: "r"(d), "l"(src));
        }
    };

    loadA(0, 0); loadB(0, 0);
    asm volatile("cp.async.commit_group;");
    if (NK > 1) {
        loadA(1, 1); loadB(1, 1);
        asm volatile("cp.async.commit_group;");
    }

    const int lo = ((g8 << 2) + t4) * 8;

    auto compute_tile = [&](int sc) {
        const __half* as = As + sc*4096;
        const __half* bs = Bs + sc*4096;
        #pragma unroll
        for (int kb = 0; kb < 2; kb++) {
            uint4 aq[4], bq[2];
            #pragma unroll
            for (int mt = 0; mt < 4; mt++)
                aq[mt] = *(const uint4*)(as + (((wrS + mt) << 1) + kb)*256 + lo);
            #pragma unroll
            for (int p = 0; p < 2; p++)
                bq[p] = *(const uint4*)(bs + (((wcS + p) << 1) + kb)*256 + lo);
            #pragma unroll
            for (int mt = 0; mt < 4; mt++) {
                #pragma unroll
                for (int p = 0; p < 2; p++) {
                    mma_f16_16n8k16(acc[mt][2*p],   (const uint32_t*)&aq[mt], bq[p].x, bq[p].z);
                    mma_f16_16n8k16(acc[mt][2*p+1], (const uint32_t*)&aq[mt], bq[p].y, bq[p].w);
                }
            }
        }
    };

    if (NK <= 8) {
        #pragma unroll
        for (int kt = 0; kt < NK; kt++) {
            if (kt + 1 < NK)
                asm volatile("cp.async.wait_group 1;");
            else
                asm volatile("cp.async.wait_group 0;");
            __syncthreads();
            if (kt + 2 < NK) {
                loadA((kt + 2) % 3, kt + 2); loadB((kt + 2) % 3, kt + 2);
                asm volatile("cp.async.commit_group;");
            }
            compute_tile(kt % 3);
            __syncthreads();
        }
    } else {
        int sc = 0;
        #pragma unroll 3
        for (int kt = 0; kt < NK; kt++) {
            if (kt + 1 < NK)
                asm volatile("cp.async.wait_group 1;");
            else
                asm volatile("cp.async.wait_group 0;");
            __syncthreads();
            if (kt + 2 < NK) {
                int sn = sc + 2; if (sn >= 3) sn -= 3;
                loadA(sn, kt + 2); loadB(sn, kt + 2);
                asm volatile("cp.async.commit_group;");
            }
            compute_tile(sc);
            __syncthreads();
            if (++sc == 3) sc = 0;
        }
    }

    #pragma unroll
    for (int mt = 0; mt < 4; mt++) {
        int r0 = mBase + wr + mt*16 + g8;
        #pragma unroll
        for (int nt = 0; nt < 4; nt++) {
            int cc = nBase + wc + nt*8 + t4*2;
            if (cc < Nvalid) {
                float bx = bias ? bias[cc]   : 0.f;
                float by = bias ? bias[cc+1] : 0.f;
                float2 v0 = make_float2(acc[mt][nt][0] + bx, acc[mt][nt][1] + by);
                float2 v1 = make_float2(acc[mt][nt][2] + bx, acc[mt][nt][3] + by);
                *(float2*)(C + (size_t)r0*ldc + cc)     = v0;
                *(float2*)(C + (size_t)(r0+8)*ldc + cc) = v1;
            }
        }
    }
}

/* =================== fused producer kernel =================== */
#define PREP_GRID 4052
__global__ void __launch_bounds__(256) k_prep(
    const float* __restrict__ hs, const int* __restrict__ pairs,
    const float* __restrict__ pos, const float* __restrict__ W1,
    const float* __restrict__ b1, const float* __restrict__ W2,
    const float* __restrict__ Wp, const float* __restrict__ Wdec) {
    __shared__ float smem_t[32*33];
    const int bx  = blockIdx.x;
    const int tid = threadIdx.x;

    if (bx < 1824) {
        const float* in; __half* out; int R, C, l, gx;
        if (bx < 1152)      { in = W1; out = g_W1T; R = K1;  C = DIM; l = bx;        gx = 24; }
        else if (bx < 1728) { in = W2; out = g_W2T; R = DIM; C = DIM; l = bx - 1152; gx = 24; }
        else                { in = Wp; out = g_WpT; R = DIM; C = EMB; l = bx - 1728; gx = 4;  }
        int c0 = (l % gx) * 32, r0 = (l / gx) * 32;
        int tx = tid & 31, ty = tid >> 5;
        float (*t)[33] = (float(*)[33])smem_t;
        #pragma unroll
        for (int dy = ty; dy < 32; dy += 8)
            t[dy][tx] = in[(size_t)(r0 + dy)*C + c0 + tx];
        __syncthreads();
        #pragma unroll
        for (int dy = ty; dy < 32; dy += 8)
            out[frag16_addr(c0 + dy, r0 + tx, R)] = h16(t[tx][dy]);
    } else if (bx < 3736) {
        int gid = (bx - 1824)*256 + tid;
        int blk = gid >> 5;
        int g   = gid & 31;
        int srow = g >> 2, t4 = g & 3;
        int R0 = (blk >> 3) << 4;
        int K0 = (blk & 7) << 4;
        int r0 = R0 + srow, r1 = r0 + 8;
        int kl = K0 + 2*t4, kh = kl + 8;
        float2 a0 = make_float2(0.f,0.f), a1 = a0, a2 = a0, a3 = a0;
        if (r0 < VOCAB) { a0 = *(const float2*)(Wdec + (size_t)r0*EMB + kl);
                          a2 = *(const float2*)(Wdec + (size_t)r0*EMB + kh); }
        if (r1 < VOCAB) { a1 = *(const float2*)(Wdec + (size_t)r1*EMB + kl);
                          a3 = *(const float2*)(Wdec + (size_t)r1*EMB + kh); }
        __half2 h0 = __floats2half2_rn(a0.x, a0.y);
        __half2 h1 = __floats2half2_rn(a1.x, a1.y);
        __half2 h2 = __floats2half2_rn(a2.x, a2.y);
        __half2 h3 = __floats2half2_rn(a3.x, a3.y);
        uint4 u = make_uint4(*(uint32_t*)&h0, *(uint32_t*)&h1, *(uint32_t*)&h2, *(uint32_t*)&h3);
        *(uint4*)(g_Wd + ((size_t)blk << 8) + (size_t)g*8) = u;
    } else if (bx < 3992) {
        if (tid < 192) {
            int p = bx - 3736;
            int l0 = pairs[p*2 + 0];
            int r0 = pairs[p*2 + 1];
            int b  = p / NP;
            const float* hl = hs + ((size_t)b*SEQ + l0)*DIM;
            const float* hr = hs + ((size_t)b*SEQ + r0)*DIM;
            int k = tid * 4;
            float4 vl = *(const float4*)(hl + k);
            float4 vr = *(const float4*)(hr + k);
            __half2 l01 = __floats2half2_rn(vl.x, vl.y);
            __half2 l23 = __floats2half2_rn(vl.z, vl.w);
            __half2 r01 = __floats2half2_rn(vr.x, vr.y);
            __half2 r23 = __floats2half2_rn(vr.z, vr.w);
            size_t aL = frag16_addr(p, k, K1);
            size_t aR = frag16_addr(p, DIM + k, K1);
            *(__half2*)(g_lr + aL)     = l01;
            *(__half2*)(g_lr + aL + 8) = l23;
            *(__half2*)(g_lr + aR)     = r01;
            *(__half2*)(g_lr + aR + 8) = r23;
        }
    } else {
        int loc = bx - 3992;
        int l = loc / 3, sub = loc % 3;
        float* sp = smem_t;
        for (int t2 = tid; t2 < PE; t2 += 256) sp[t2] = pos[l*PE + t2];
        __syncthreads();
        int j = sub*256 + tid;
        float acc = b1[j];
        const float* w = W1 + (size_t)K1*DIM + j;
        #pragma unroll 8
        for (int t2 = 0; t2 < PE; t2++) acc += sp[t2] * w[(size_t)t2*DIM];
        g_P[l*DIM + j] = acc;
    }
}

/* =================== LN kernels: 192 thr x 4 consecutive j =============== */
__device__ __forceinline__ void block_reduce2_192(float& s, float& sq) {
    __shared__ float ss[6], ssq[6];
    #pragma unroll
    for (int o = 16; o > 0; o >>= 1) {
        s  += __shfl_xor_sync(0xffffffffu, s,  o);
        sq += __shfl_xor_sync(0xffffffffu, sq, o);
    }
    int w = threadIdx.x >> 5;
    if ((threadIdx.x & 31) == 0) { ss[w] = s; ssq[w] = sq; }
    __syncthreads();
    s = 0.f; sq = 0.f;
    #pragma unroll
    for (int i = 0; i < 6; i++) { s += ss[i]; sq += ssq[i]; }
}

__global__ void __launch_bounds__(192) k_fuse1(const float* __restrict__ part,
                        const float* __restrict__ g1, const float* __restrict__ be1) {
    int r = blockIdx.x;
    int p = r / SPAN, l = r % SPAN;
    int j = threadIdx.x * 4;
    float4 a4 = *(const float4*)(g_P + (size_t)l*DIM + j);
    float a[4] = {a4.x, a4.y, a4.z, a4.w};
    #pragma unroll
    for (int z = 0; z < 8; z++) {
        float4 pz = *(const float4*)(part + (size_t)z*(NB*DIM) + (size_t)p*DIM + j);
        a[0] += pz.x; a[1] += pz.y; a[2] += pz.z; a[3] += pz.w;
    }
    float v[4];
    float s = 0.f, sq = 0.f;
    #pragma unroll
    for (int q = 0; q < 4; q++) {
        v[q] = gelu_exact(a[q]); s += v[q]; sq += v[q]*v[q];
    }
    block_reduce2_192(s, sq);
    float mean = s * (1.0f/DIM);
    float var  = sq * (1.0f/DIM) - mean*mean;
    float rstd = rsqrtf(var + 1e-12f);
    float4 gg = *(const float4*)(g1 + j);
    float4 bb = *(const float4*)(be1 + j);
    float o0 = (v[0]-mean)*rstd*gg.x + bb.x;
    float o1 = (v[1]-mean)*rstd*gg.y + bb.y;
    float o2 = (v[2]-mean)*rstd*gg.z + bb.z;
    float o3 = (v[3]-mean)*rstd*gg.w + bb.w;
    size_t ad = frag16_addr(r, j, DIM);
    *(__half2*)(g_h1 + ad)     = __floats2half2_rn(o0, o1);
    *(__half2*)(g_h1 + ad + 8) = __floats2half2_rn(o2, o3);
}

__global__ void __launch_bounds__(192) k_gelu_ln(const float* __restrict__ in,
                          const float* __restrict__ g, const float* __restrict__ be) {
    int r = blockIdx.x;
    int j = threadIdx.x * 4;
    float4 a4 = *(const float4*)(in + (size_t)r*DIM + j);
    float v[4];
    float s = 0.f, sq = 0.f;
    v[0] = gelu_exact(a4.x); v[1] = gelu_exact(a4.y);
    v[2] = gelu_exact(a4.z); v[3] = gelu_exact(a4.w);
    #pragma unroll
    for (int q = 0; q < 4; q++) { s += v[q]; sq += v[q]*v[q]; }
    block_reduce2_192(s, sq);
    float mean = s * (1.0f/DIM);
    float var  = sq * (1.0f/DIM) - mean*mean;
    float rstd = rsqrtf(var + 1e-12f);
    float4 gg = *(const float4*)(g + j);
    float4 bb = *(const float4*)(be + j);
    float o0 = (v[0]-mean)*rstd*gg.x + bb.x;
    float o1 = (v[1]-mean)*rstd*gg.y + bb.y;
    float o2 = (v[2]-mean)*rstd*gg.z + bb.z;
    float o3 = (v[3]-mean)*rstd*gg.w + bb.w;
    size_t ad = frag16_addr(r, j, DIM);
    *(__half2*)(g_h2 + ad)     = __floats2half2_rn(o0, o1);
    *(__half2*)(g_h2 + ad + 8) = __floats2half2_rn(o2, o3);
}

__global__ void __launch_bounds__(256) k_reduceh3(const float* __restrict__ part,
                                                  const float* __restrict__ bp) {
    int i = (blockIdx.x*256 + threadIdx.x) * 4;
    float4 b4 = *(const float4*)(bp + (i & 127));
    float s0 = b4.x, s1 = b4.y, s2 = b4.z, s3 = b4.w;
    #pragma unroll
    for (int z = 0; z < 4; z++) {
        float4 pz = *(const float4*)(part + (size_t)z*(NR*EMB) + i);
        s0 += pz.x; s1 += pz.y; s2 += pz.z; s3 += pz.w;
    }
    size_t ad = frag16_addr(i >> 7, i & 127, EMB);
    *(__half2*)(g_h3 + ad)     = __floats2half2_rn(s0, s1);
    *(__half2*)(g_h3 + ad + 8) = __floats2half2_rn(s2, s3);
}

/* ---------------- host launch ---------------- */
extern "C" void kernel_launch(void* const* d_in, const int* in_sizes, int n_in,
                              void* d_out, int out_size) {
    const float* hs    = (const float*)d_in[0];
    const int*   pairs = (const int*)  d_in[1];
    const float* pos   = (const float*)d_in[2];
    const float* W1    = (const float*)d_in[3];
    const float* b1    = (const float*)d_in[4];
    const float* g1    = (const float*)d_in[5];
    const float* be1   = (const float*)d_in[6];
    const float* W2    = (const float*)d_in[7];
    const float* b2    = (const float*)d_in[8];
    const float* g2    = (const float*)d_in[9];
    const float* be2   = (const float*)d_in[10];
    const float* Wp    = (const float*)d_in[11];
    const float* bp    = (const float*)d_in[12];
    const float* Wdec  = (const float*)d_in[13];
    float* out = (float*)d_out;
    (void)in_sizes; (void)n_in; (void)out_size;

    __half *p_lr, *p_h1, *p_h2, *p_h3, *p_W1T, *p_W2T, *p_WpT, *p_Wd;
    float *p_pre2;
    cudaGetSymbolAddress((void**)&p_lr,   g_lr);
    cudaGetSymbolAddress((void**)&p_h1,   g_h1);
    cudaGetSymbolAddress((void**)&p_h2,   g_h2);
    cudaGetSymbolAddress((void**)&p_h3,   g_h3);
    cudaGetSymbolAddress((void**)&p_W1T,  g_W1T);
    cudaGetSymbolAddress((void**)&p_W2T,  g_W2T);
    cudaGetSymbolAddress((void**)&p_WpT,  g_WpT);
    cudaGetSymbolAddress((void**)&p_Wd,   g_Wd);
    cudaGetSymbolAddress((void**)&p_pre2, g_pre2);

    const int MSMEM = 6 * 4096 * 2;   /* 49152 B */
    cudaFuncSetAttribute(mgemm16<192>, cudaFuncAttributeMaxDynamicSharedMemorySize, MSMEM);
    cudaFuncSetAttribute(mgemm16<768>, cudaFuncAttributeMaxDynamicSharedMemorySize, MSMEM);
    cudaFuncSetAttribute(mgemm16<128>, cudaFuncAttributeMaxDynamicSharedMemorySize, MSMEM);

    /* 0) one fused producer launch */
    k_prep<<<PREP_GRID, 256>>>(hs, pairs, pos, W1, b1, W2, Wp, Wdec);

    /* 1) A-partials = g_lr @ W1[0:1536]  split-K x8 (into g_pre2) */
    mgemm16<192><<<dim3(DIM/128, NB/128, 8), 256, MSMEM>>>(
        p_lr, K1, p_W1T, K1, DIM, p_pre2, DIM, nullptr, NB*DIM);

    /* 2) h1 = LN(gelu(sum partials + P)) -> FRAG16 */
    k_fuse1<<<NR, 192>>>(p_pre2, g1, be1);

    /* 3) pre2 = h1 @ W2 + b2 ; h2 = LN(gelu(pre2)) -> FRAG16 */
    mgemm16<768><<<dim3(DIM/128, NR/128, 1), 256, MSMEM>>>(
        p_h1, DIM, p_W2T, DIM, DIM, p_pre2, DIM, b2, 0);
    k_gelu_ln<<<NR, 192>>>(p_pre2, g2, be2);

    /* 4) h3 = h2 @ Wp + bp  split-K x4 -> FRAG16 via reduce */
    mgemm16<192><<<dim3(EMB/128, NR/128, 4), 256, MSMEM>>>(
        p_h2, DIM, p_WpT, DIM, EMB, p_pre2, EMB, nullptr, NR*EMB);
    k_reduceh3<<<(NR*EMB)/1024, 256>>>(p_pre2, bp);

    /* 5) out = h3 @ Wd^T (M=5120 N=30522(+pad) K=128) */
    mgemm16<128><<<dim3(VROWS/128, NR/128, 1), 256, MSMEM>>>(
        p_h3, EMB, p_Wd, EMB, VOCAB, out, VOCAB, nullptr, 0);
}

// round 13
// speedup vs baseline: 2.2899x; 1.0019x over previous
#include <cuda_runtime.h>
#include <cuda_fp16.h>
#include <math.h>
#include <stdint.h>

#define BSZ   8
#define SEQ   512
#define DIM   768
#define NP    32
#define PE    200
#define EMB   128
#define VOCAB 30522
#define SPAN  20
#define NB    (BSZ*NP)        /* 256 span pairs */
#define NR    (NB*SPAN)       /* 5120 rows */
#define K1    1536            /* 2*DIM */
#define VROWS 30592           /* 239*128, padded vocab rows */

/* ---------------- scratch (no allocation allowed) ---------------- */
__device__ __align__(256) __half g_lr[NB*K1];
__device__ __align__(256) __half g_h1[NR*DIM];
__device__ __align__(256) __half g_h2[NR*DIM];
__device__ __align__(256) __half g_h3[NR*EMB];
__device__ __align__(256) __half g_W1T[DIM*K1];
__device__ __align__(256) __half g_W2T[DIM*DIM];
__device__ __align__(256) __half g_WpT[EMB*DIM];
__device__ __align__(256) __half g_Wd[VROWS*EMB];
__device__ float g_P[SPAN*DIM];
__device__ float g_pre2[NR*DIM];     /* split-K partial scratch / pre2 */

/* FRAG16: block = 16 rows x 16 k = 256 halves. Granule (16B) at (srow,t4)
 * holds m16n8k16 A-quad. For fixed r and k%4==0: (r,k),(r,k+1) adjacent
 * halves; (r,k+2),(r,k+3) at +8 halves. */
__device__ __forceinline__ size_t frag16_addr(int r, int k, int ld) {
    size_t blk = (size_t)((r >> 4) * (ld >> 4) + (k >> 4));
    int kk = k & 15;
    return (blk << 8) + (((r & 7) << 2) + ((kk >> 1) & 3)) * 8
         + ((((r >> 3) & 1) + ((kk >> 3) << 1)) << 1) + (kk & 1);
}

__device__ __forceinline__ float gelu_exact(float x) {
    return 0.5f * x * (1.0f + erff(x * 0.70710678118654752440f));
}
__device__ __forceinline__ __half h16(float x) { return __float2half_rn(x); }

__device__ __forceinline__ void mma_f16_16n8k16(float* c, const uint32_t* a,
                                                uint32_t b0, uint32_t b1) {
    asm volatile(
        "mma.sync.aligned.m16n8k16.row.col.f32.f16.f16.f32 "
        "{%0,%1,%2,%3}, {%4,%5,%6,%7}, {%8,%9}, {%0,%1,%2,%3};"
        : "+f"(c[0]), "+f"(c[1]), "+f"(c[2]), "+f"(c[3])
        : "r"(a[0]), "r"(a[1]), "r"(a[2]), "r"(a[3]), "r"(b0), "r"(b1));
}

__device__ __forceinline__ uint32_t smem_u32(const void* p) {
    uint32_t a;
    asm("{ .reg .u64 t; cvta.to.shared.u64 t, %1; cvt.u32.u64 %0, t; }" : "=r"(a) : "l"(p));
    return a;
}

/* =================== fp16 mma.sync GEMM (FRAG16, BK=64, 3-stage) =========
 * 256 threads / 8 warps, warp tile 64x32. CTA tile 128x128, BK=64.
 * Stage = A(8192) + B(8192) halves = 32KB; 3 stages = 96KB; 2 CTAs/SM.
 * ONE __syncthreads per k-tile (trailing barrier provably redundant with
 * 3 stages: loads at iter kt overwrite stage (kt-1)%3, whose readers all
 * passed the leading barrier of iter kt).
 */
template<int KC>
__global__ void __launch_bounds__(256, 2)
mgemm16(const __half* __restrict__ A, int lda,
        const __half* __restrict__ Bt, int ldb, int Nvalid,
        float* __restrict__ C, int ldc,
        const float* __restrict__ bias, int czstride) {
    constexpr int NK = KC >> 6;      /* 64-K tiles */
    constexpr int STG = 8192;        /* halves per stage per operand */
    extern __shared__ __align__(16) __half sm16[];
    __half* As = sm16;               /* [3][8192] */
    __half* Bs = sm16 + 3*STG;
    const uint32_t sbA = smem_u32(As);
    const uint32_t sbB = smem_u32(Bs);

    const int tid  = threadIdx.x;
    const int lane = tid & 31;
    const int wid  = tid >> 5;
    const int wr   = (wid & 1) * 64;   /* warp rows: 2 groups */
    const int wc   = (wid >> 1) * 32;  /* warp cols: 4 groups */
    const int wrS  = (wid & 1) * 4;    /* row slabs */
    const int wcS  = (wid >> 1) * 2;   /* col slabs */
    const int g8   = lane >> 2;
    const int t4   = lane & 3;

    const int mBase = blockIdx.y * 128;
    const int nBase = blockIdx.x * 128;
    const int mSlab = mBase >> 4;
    const int nSlab = nBase >> 4;
    const int k0    = blockIdx.z * KC;
    C += (size_t)blockIdx.z * czstride;
    const int ldaB = lda >> 4;
    const int ldbB = ldb >> 4;

    float acc[4][4][4];
    #pragma unroll
    for (int i = 0; i < 4; i++)
        #pragma unroll
        for (int j = 0; j < 4; j++)
            #pragma unroll
            for (int q = 0; q < 4; q++) acc[i][j][q] = 0.f;

    /* stage = 1024 granules (16B); 256 thr x 4. slab=idx>>7, kb=(idx>>5)&3 */
    auto loadA = [&](int s, int kt) {
        const int kbase = (k0 >> 4) + kt*4;
        #pragma unroll
        for (int i = 0; i < 4; i++) {
            int idx  = tid + i*256;
            int slab = idx >> 7;
            int kb   = (idx >> 5) & 3;
            int g    = idx & 31;
            const __half* src = A + (((size_t)(mSlab + slab)*ldaB + (kbase + kb)) << 8) + g*8;
            uint32_t d = sbA + (uint32_t)(s*STG + ((slab << 2) + kb)*256 + g*8)*2u;
            asm volatile("cp.async.cg.shared.global [%0], [%1], 16;" :: "r"(d), "l"(src));
        }
    };
    auto loadB = [&](int s, int kt) {
        const int kbase = (k0 >> 4) + kt*4;
        #pragma unroll
        for (int i = 0; i < 4; i++) {
            int idx  = tid + i*256;
            int slab = idx >> 7;
            int kb   = (idx >> 5) & 3;
            int g    = idx & 31;
            const __half* src = Bt + (((size_t)(nSlab + slab)*ldbB + (kbase + kb)) << 8) + g*8;
            uint32_t d = sbB + (uint32_t)(s*STG + ((slab << 2) + kb)*256 + g*8)*2u;
            asm volatile("cp.async.cg.shared.global [%0], [%1], 16;" :: "r"(d), "l"(src));
        }
    };

    loadA(0, 0); loadB(0, 0);
    asm volatile("cp.async.commit_group;");
    if (NK > 1) {
        loadA(1, 1); loadB(1, 1);
        asm volatile("cp.async.commit_group;");
    }

    const int lo = ((g8 << 2) + t4) * 8;

    auto compute_tile = [&](int sc) {
        const __half* as = As + sc*STG;
        const __half* bs = Bs + sc*STG;
        #pragma unroll
        for (int kb = 0; kb < 4; kb++) {
            uint4 aq[4], bq[2];
            #pragma unroll
            for (int mt = 0; mt < 4; mt++)
                aq[mt] = *(const uint4*)(as + (((wrS + mt) << 2) + kb)*256 + lo);
            #pragma unroll
            for (int p = 0; p < 2; p++)
                bq[p] = *(const uint4*)(bs + (((wcS + p) << 2) + kb)*256 + lo);
            #pragma unroll
            for (int mt = 0; mt < 4; mt++) {
                #pragma unroll
                for (int p = 0; p < 2; p++) {
                    mma_f16_16n8k16(acc[mt][2*p],   (const uint32_t*)&aq[mt], bq[p].x, bq[p].z);
                    mma_f16_16n8k16(acc[mt][2*p+1], (const uint32_t*)&aq[mt], bq[p].y, bq[p].w);
                }
            }
        }
    };

    if (NK <= 8) {
        #pragma unroll
        for (int kt = 0; kt < NK; kt++) {
            if (kt + 1 < NK)
                asm volatile("cp.async.wait_group 1;");
            else
                asm volatile("cp.async.wait_group 0;");
            __syncthreads();
            if (kt + 2 < NK) {
                loadA((kt + 2) % 3, kt + 2); loadB((kt + 2) % 3, kt + 2);
                asm volatile("cp.async.commit_group;");
            }
            compute_tile(kt % 3);
        }
    } else {
        int sc = 0;
        #pragma unroll 3
        for (int kt = 0; kt < NK; kt++) {
            if (kt + 1 < NK)
                asm volatile("cp.async.wait_group 1;");
            else
                asm volatile("cp.async.wait_group 0;");
            __syncthreads();
            if (kt + 2 < NK) {
                int sn = sc + 2; if (sn >= 3) sn -= 3;
                loadA(sn, kt + 2); loadB(sn, kt + 2);
                asm volatile("cp.async.commit_group;");
            }
            compute_tile(sc);
            if (++sc == 3) sc = 0;
        }
    }

    #pragma unroll
    for (int mt = 0; mt < 4; mt++) {
        int r0 = mBase + wr + mt*16 + g8;
        #pragma unroll
        for (int nt = 0; nt < 4; nt++) {
            int cc = nBase + wc + nt*8 + t4*2;
            if (cc < Nvalid) {
                float bx = bias ? bias[cc]   : 0.f;
                float by = bias ? bias[cc+1] : 0.f;
                float2 v0 = make_float2(acc[mt][nt][0] + bx, acc[mt][nt][1] + by);
                float2 v1 = make_float2(acc[mt][nt][2] + bx, acc[mt][nt][3] + by);
                *(float2*)(C + (size_t)r0*ldc + cc)     = v0;
                *(float2*)(C + (size_t)(r0+8)*ldc + cc) = v1;
            }
        }
    }
}

/* =================== fused producer kernel =================== */
#define PREP_GRID 4052
__global__ void __launch_bounds__(256) k_prep(
    const float* __restrict__ hs, const int* __restrict__ pairs,
    const float* __restrict__ pos, const float* __restrict__ W1,
    const float* __restrict__ b1, const float* __restrict__ W2,
    const float* __restrict__ Wp, const float* __restrict__ Wdec) {
    __shared__ float smem_t[32*33];
    const int bx  = blockIdx.x;
    const int tid = threadIdx.x;

    if (bx < 1824) {
        const float* in; __half* out; int R, C, l, gx;
        if (bx < 1152)      { in = W1; out = g_W1T; R = K1;  C = DIM; l = bx;        gx = 24; }
        else if (bx < 1728) { in = W2; out = g_W2T; R = DIM; C = DIM; l = bx - 1152; gx = 24; }
        else                { in = Wp; out = g_WpT; R = DIM; C = EMB; l = bx - 1728; gx = 4;  }
        int c0 = (l % gx) * 32, r0 = (l / gx) * 32;
        int tx = tid & 31, ty = tid >> 5;
        float (*t)[33] = (float(*)[33])smem_t;
        #pragma unroll
        for (int dy = ty; dy < 32; dy += 8)
            t[dy][tx] = in[(size_t)(r0 + dy)*C + c0 + tx];
        __syncthreads();
        #pragma unroll
        for (int dy = ty; dy < 32; dy += 8)
            out[frag16_addr(c0 + dy, r0 + tx, R)] = h16(t[tx][dy]);
    } else if (bx < 3736) {
        int gid = (bx - 1824)*256 + tid;
        int blk = gid >> 5;
        int g   = gid & 31;
        int srow = g >> 2, t4 = g & 3;
        int R0 = (blk >> 3) << 4;
        int K0 = (blk & 7) << 4;
        int r0 = R0 + srow, r1 = r0 + 8;
        int kl = K0 + 2*t4, kh = kl + 8;
        float2 a0 = make_float2(0.f,0.f), a1 = a0, a2 = a0, a3 = a0;
        if (r0 < VOCAB) { a0 = *(const float2*)(Wdec + (size_t)r0*EMB + kl);
                          a2 = *(const float2*)(Wdec + (size_t)r0*EMB + kh); }
        if (r1 < VOCAB) { a1 = *(const float2*)(Wdec + (size_t)r1*EMB + kl);
                          a3 = *(const float2*)(Wdec + (size_t)r1*EMB + kh); }
        __half2 h0 = __floats2half2_rn(a0.x, a0.y);
        __half2 h1 = __floats2half2_rn(a1.x, a1.y);
        __half2 h2 = __floats2half2_rn(a2.x, a2.y);
        __half2 h3 = __floats2half2_rn(a3.x, a3.y);
        uint4 u = make_uint4(*(uint32_t*)&h0, *(uint32_t*)&h1, *(uint32_t*)&h2, *(uint32_t*)&h3);
        *(uint4*)(g_Wd + ((size_t)blk << 8) + (size_t)g*8) = u;
    } else if (bx < 3992) {
        if (tid < 192) {
            int p = bx - 3736;
            int l0 = pairs[p*2 + 0];
            int r0 = pairs[p*2 + 1];
            int b  = p / NP;
            const float* hl = hs + ((size_t)b*SEQ + l0)*DIM;
            const float* hr = hs + ((size_t)b*SEQ + r0)*DIM;
            int k = tid * 4;
            float4 vl = *(const float4*)(hl + k);
            float4 vr = *(const float4*)(hr + k);
            __half2 l01 = __floats2half2_rn(vl.x, vl.y);
            __half2 l23 = __floats2half2_rn(vl.z, vl.w);
            __half2 r01 = __floats2half2_rn(vr.x, vr.y);
            __half2 r23 = __floats2half2_rn(vr.z, vr.w);
            size_t aL = frag16_addr(p, k, K1);
            size_t aR = frag16_addr(p, DIM + k, K1);
            *(__half2*)(g_lr + aL)     = l01;
            *(__half2*)(g_lr + aL + 8) = l23;
            *(__half2*)(g_lr + aR)     = r01;
            *(__half2*)(g_lr + aR + 8) = r23;
        }
    } else {
        int loc = bx - 3992;
        int l = loc / 3, sub = loc % 3;
        float* sp = smem_t;
        for (int t2 = tid; t2 < PE; t2 += 256) sp[t2] = pos[l*PE + t2];
        __syncthreads();
        int j = sub*256 + tid;
        float acc = b1[j];
        const float* w = W1 + (size_t)K1*DIM + j;
        #pragma unroll 8
        for (int t2 = 0; t2 < PE; t2++) acc += sp[t2] * w[(size_t)t2*DIM];
        g_P[l*DIM + j] = acc;
    }
}

/* =================== LN kernels: 192 thr x 4 consecutive j =============== */
__device__ __forceinline__ void block_reduce2_192(float& s, float& sq) {
    __shared__ float ss[6], ssq[6];
    #pragma unroll
    for (int o = 16; o > 0; o >>= 1) {
        s  += __shfl_xor_sync(0xffffffffu, s,  o);
        sq += __shfl_xor_sync(0xffffffffu, sq, o);
    }
    int w = threadIdx.x >> 5;
    if ((threadIdx.x & 31) == 0) { ss[w] = s; ssq[w] = sq; }
    __syncthreads();
    s = 0.f; sq = 0.f;
    #pragma unroll
    for (int i = 0; i < 6; i++) { s += ss[i]; sq += ssq[i]; }
}

__global__ void __launch_bounds__(192) k_fuse1(const float* __restrict__ part,
                        const float* __restrict__ g1, const float* __restrict__ be1) {
    int r = blockIdx.x;
    int p = r / SPAN, l = r % SPAN;
    int j = threadIdx.x * 4;
    float4 a4 = *(const float4*)(g_P + (size_t)l*DIM + j);
    float a[4] = {a4.x, a4.y, a4.z, a4.w};
    #pragma unroll
    for (int z = 0; z < 8; z++) {
        float4 pz = *(const float4*)(part + (size_t)z*(NB*DIM) + (size_t)p*DIM + j);
        a[0] += pz.x; a[1] += pz.y; a[2] += pz.z; a[3] += pz.w;
    }
    float v[4];
    float s = 0.f, sq = 0.f;
    #pragma unroll
    for (int q = 0; q < 4; q++) {
        v[q] = gelu_exact(a[q]); s += v[q]; sq += v[q]*v[q];
    }
    block_reduce2_192(s, sq);
    float mean = s * (1.0f/DIM);
    float var  = sq * (1.0f/DIM) - mean*mean;
    float rstd = rsqrtf(var + 1e-12f);
    float4 gg = *(const float4*)(g1 + j);
    float4 bb = *(const float4*)(be1 + j);
    float o0 = (v[0]-mean)*rstd*gg.x + bb.x;
    float o1 = (v[1]-mean)*rstd*gg.y + bb.y;
    float o2 = (v[2]-mean)*rstd*gg.z + bb.z;
    float o3 = (v[3]-mean)*rstd*gg.w + bb.w;
    size_t ad = frag16_addr(r, j, DIM);
    *(__half2*)(g_h1 + ad)     = __floats2half2_rn(o0, o1);
    *(__half2*)(g_h1 + ad + 8) = __floats2half2_rn(o2, o3);
}

__global__ void __launch_bounds__(192) k_gelu_ln(const float* __restrict__ in,
                          const float* __restrict__ g, const float* __restrict__ be) {
    int r = blockIdx.x;
    int j = threadIdx.x * 4;
    float4 a4 = *(const float4*)(in + (size_t)r*DIM + j);
    float v[4];
    float s = 0.f, sq = 0.f;
    v[0] = gelu_exact(a4.x); v[1] = gelu_exact(a4.y);
    v[2] = gelu_exact(a4.z); v[3] = gelu_exact(a4.w);
    #pragma unroll
    for (int q = 0; q < 4; q++) { s += v[q]; sq += v[q]*v[q]; }
    block_reduce2_192(s, sq);
    float mean = s * (1.0f/DIM);
    float var  = sq * (1.0f/DIM) - mean*mean;
    float rstd = rsqrtf(var + 1e-12f);
    float4 gg = *(const float4*)(g + j);
    float4 bb = *(const float4*)(be + j);
    float o0 = (v[0]-mean)*rstd*gg.x + bb.x;
    float o1 = (v[1]-mean)*rstd*gg.y + bb.y;
    float o2 = (v[2]-mean)*rstd*gg.z + bb.z;
    float o3 = (v[3]-mean)*rstd*gg.w + bb.w;
    size_t ad = frag16_addr(r, j, DIM);
    *(__half2*)(g_h2 + ad)     = __floats2half2_rn(o0, o1);
    *(__half2*)(g_h2 + ad + 8) = __floats2half2_rn(o2, o3);
}

__global__ void __launch_bounds__(256) k_reduceh3(const float* __restrict__ part,
                                                  const float* __restrict__ bp) {
    int i = (blockIdx.x*256 + threadIdx.x) * 4;
    float4 b4 = *(const float4*)(bp + (i & 127));
    float s0 = b4.x, s1 = b4.y, s2 = b4.z, s3 = b4.w;
    #pragma unroll
    for (int z = 0; z < 4; z++) {
        float4 pz = *(const float4*)(part + (size_t)z*(NR*EMB) + i);
        s0 += pz.x; s1 += pz.y; s2 += pz.z; s3 += pz.w;
    }
    size_t ad = frag16_addr(i >> 7, i & 127, EMB);
    *(__half2*)(g_h3 + ad)     = __floats2half2_rn(s0, s1);
    *(__half2*)(g_h3 + ad + 8) = __floats2half2_rn(s2, s3);
}

/* ---------------- host launch ---------------- */
extern "C" void kernel_launch(void* const* d_in, const int* in_sizes, int n_in,
                              void* d_out, int out_size) {
    const float* hs    = (const float*)d_in[0];
    const int*   pairs = (const int*)  d_in[1];
    const float* pos   = (const float*)d_in[2];
    const float* W1    = (const float*)d_in[3];
    const float* b1    = (const float*)d_in[4];
    const float* g1    = (const float*)d_in[5];
    const float* be1   = (const float*)d_in[6];
    const float* W2    = (const float*)d_in[7];
    const float* b2    = (const float*)d_in[8];
    const float* g2    = (const float*)d_in[9];
    const float* be2   = (const float*)d_in[10];
    const float* Wp    = (const float*)d_in[11];
    const float* bp    = (const float*)d_in[12];
    const float* Wdec  = (const float*)d_in[13];
    float* out = (float*)d_out;
    (void)in_sizes; (void)n_in; (void)out_size;

    __half *p_lr, *p_h1, *p_h2, *p_h3, *p_W1T, *p_W2T, *p_WpT, *p_Wd;
    float *p_pre2;
    cudaGetSymbolAddress((void**)&p_lr,   g_lr);
    cudaGetSymbolAddress((void**)&p_h1,   g_h1);
    cudaGetSymbolAddress((void**)&p_h2,   g_h2);
    cudaGetSymbolAddress((void**)&p_h3,   g_h3);
    cudaGetSymbolAddress((void**)&p_W1T,  g_W1T);
    cudaGetSymbolAddress((void**)&p_W2T,  g_W2T);
    cudaGetSymbolAddress((void**)&p_WpT,  g_WpT);
    cudaGetSymbolAddress((void**)&p_Wd,   g_Wd);
    cudaGetSymbolAddress((void**)&p_pre2, g_pre2);

    const int MSMEM = 6 * 8192 * 2;   /* 3 stages x (A+B) x 16KB = 98304 B */
    cudaFuncSetAttribute(mgemm16<192>, cudaFuncAttributeMaxDynamicSharedMemorySize, MSMEM);
    cudaFuncSetAttribute(mgemm16<768>, cudaFuncAttributeMaxDynamicSharedMemorySize, MSMEM);
    cudaFuncSetAttribute(mgemm16<128>, cudaFuncAttributeMaxDynamicSharedMemorySize, MSMEM);

    /* 0) one fused producer launch */
    k_prep<<<PREP_GRID, 256>>>(hs, pairs, pos, W1, b1, W2, Wp, Wdec);

    /* 1) A-partials = g_lr @ W1[0:1536]  split-K x8 (into g_pre2) */
    mgemm16<192><<<dim3(DIM/128, NB/128, 8), 256, MSMEM>>>(
        p_lr, K1, p_W1T, K1, DIM, p_pre2, DIM, nullptr, NB*DIM);

    /* 2) h1 = LN(gelu(sum partials + P)) -> FRAG16 */
    k_fuse1<<<NR, 192>>>(p_pre2, g1, be1);

    /* 3) pre2 = h1 @ W2 + b2 ; h2 = LN(gelu(pre2)) -> FRAG16 */
    mgemm16<768><<<dim3(DIM/128, NR/128, 1), 256, MSMEM>>>(
        p_h1, DIM, p_W2T, DIM, DIM, p_pre2, DIM, b2, 0);
    k_gelu_ln<<<NR, 192>>>(p_pre2, g2, be2);

    /* 4) h3 = h2 @ Wp + bp  split-K x4 -> FRAG16 via reduce */
    mgemm16<192><<<dim3(EMB/128, NR/128, 4), 256, MSMEM>>>(
        p_h2, DIM, p_WpT, DIM, EMB, p_pre2, EMB, nullptr, NR*EMB);
    k_reduceh3<<<(NR*EMB)/1024, 256>>>(p_pre2, bp);

    /* 5) out = h3 @ Wd^T (M=5120 N=30522(+pad) K=128) */
    mgemm16<128><<<dim3(VROWS/128, NR/128, 1), 256, MSMEM>>>(
        p_h3, EMB, p_Wd, EMB, VOCAB, out, VOCAB, nullptr, 0);
}